// round 10
// baseline (speedup 1.0000x reference)
#include <cuda_runtime.h>
#include <cuda_bf16.h>
#include <math.h>

// Problem constants
#define BATCH 8
#define SEQ   2048
#define DIM   512
#define KDIM  1024
#define MTOT  (BATCH*SEQ)   // 16384

// Scratch (no cudaMalloc allowed)
__device__ __nv_bfloat16 g_Ah[(size_t)MTOT * KDIM];
__device__ __nv_bfloat16 g_Al[(size_t)MTOT * KDIM];
__device__ __nv_bfloat16 g_Wh[(size_t)3 * DIM * KDIM];
__device__ __nv_bfloat16 g_Wl[(size_t)3 * DIM * KDIM];
__device__ __nv_bfloat16 g_qh[(size_t)MTOT * DIM];
__device__ __nv_bfloat16 g_ql[(size_t)MTOT * DIM];
__device__ __nv_bfloat16 g_kh[(size_t)MTOT * DIM];
__device__ __nv_bfloat16 g_kl[(size_t)MTOT * DIM];
__device__ __nv_bfloat16 g_vh[(size_t)MTOT * DIM];
__device__ __nv_bfloat16 g_vl[(size_t)MTOT * DIM];

// ---------------------------------------------------------------------------
// helpers
// ---------------------------------------------------------------------------
__device__ __forceinline__ unsigned smem_u32(const void* p) {
    unsigned a;
    asm("{ .reg .u64 t; cvta.to.shared.u64 t, %1; cvt.u32.u64 %0, t; }" : "=r"(a) : "l"(p));
    return a;
}
__device__ __forceinline__ void cpa16(unsigned dst, const void* src) {
    asm volatile("cp.async.cg.shared.global [%0], [%1], 16;"
                 :: "r"(dst), "l"(__cvta_generic_to_global(src)) : "memory");
}
__device__ __forceinline__ void cp_commit() {
    asm volatile("cp.async.commit_group;" ::: "memory");
}
template <int N>
__device__ __forceinline__ void cp_wait() {
    asm volatile("cp.async.wait_group %0;" :: "n"(N) : "memory");
}
__device__ __forceinline__ void ldsm4(unsigned* r, unsigned addr) {
    asm volatile("ldmatrix.sync.aligned.m8n8.x4.shared.b16 {%0,%1,%2,%3}, [%4];"
                 : "=r"(r[0]), "=r"(r[1]), "=r"(r[2]), "=r"(r[3]) : "r"(addr));
}
__device__ __forceinline__ void ldsm4t(unsigned* r, unsigned addr) {
    asm volatile("ldmatrix.sync.aligned.m8n8.x4.trans.shared.b16 {%0,%1,%2,%3}, [%4];"
                 : "=r"(r[0]), "=r"(r[1]), "=r"(r[2]), "=r"(r[3]) : "r"(addr));
}
__device__ __forceinline__ void mma_bf16(float* c, const unsigned* a,
                                         unsigned b0, unsigned b1) {
    asm volatile(
        "mma.sync.aligned.m16n8k16.row.col.f32.bf16.bf16.f32 "
        "{%0,%1,%2,%3}, {%4,%5,%6,%7}, {%8,%9}, {%0,%1,%2,%3};"
        : "+f"(c[0]), "+f"(c[1]), "+f"(c[2]), "+f"(c[3])
        : "r"(a[0]), "r"(a[1]), "r"(a[2]), "r"(a[3]), "r"(b0), "r"(b1));
}

// ---------------------------------------------------------------------------
// Conversion: x0|x1 -> bf16 hi/lo, row-major [MTOT][1024]
// ---------------------------------------------------------------------------
__global__ __launch_bounds__(256)
void conv_x(const float* __restrict__ x0, const float* __restrict__ x1)
{
    unsigned t = blockIdx.x * 256u + threadIdx.x;
    unsigned m  = t >> 8;
    unsigned k4 = (t & 255u) * 4u;
    float4 v = (k4 < 512u)
        ? *(const float4*)(x0 + (size_t)m * 512 + k4)
        : *(const float4*)(x1 + (size_t)m * 512 + (k4 - 512u));
    __nv_bfloat16 h0 = __float2bfloat16(v.x);
    __nv_bfloat16 h1 = __float2bfloat16(v.y);
    __nv_bfloat16 h2 = __float2bfloat16(v.z);
    __nv_bfloat16 h3 = __float2bfloat16(v.w);
    __nv_bfloat16 l0 = __float2bfloat16(v.x - __bfloat162float(h0));
    __nv_bfloat16 l1 = __float2bfloat16(v.y - __bfloat162float(h1));
    __nv_bfloat16 l2 = __float2bfloat16(v.z - __bfloat162float(h2));
    __nv_bfloat16 l3 = __float2bfloat16(v.w - __bfloat162float(h3));
    size_t o = (size_t)m * 1024 + k4;
    __nv_bfloat162* dh = (__nv_bfloat162*)(g_Ah + o);
    __nv_bfloat162* dl = (__nv_bfloat162*)(g_Al + o);
    dh[0] = __nv_bfloat162(h0, h1); dh[1] = __nv_bfloat162(h2, h3);
    dl[0] = __nv_bfloat162(l0, l1); dl[1] = __nv_bfloat162(l2, l3);
}

// ---------------------------------------------------------------------------
// W[k][n] -> W^T hi/lo bf16, n-major rows (q scaled by 1/sqrt(D))
// ---------------------------------------------------------------------------
__global__ __launch_bounds__(256)
void conv_w(const float* __restrict__ Wq, const float* __restrict__ Wk,
            const float* __restrict__ Wv)
{
    __shared__ float tile[32][33];
    const int z  = blockIdx.z;
    const float* __restrict__ W = (z == 0) ? Wq : ((z == 1) ? Wk : Wv);
    const int n0 = blockIdx.x * 32;
    const int k0 = blockIdx.y * 32;
    const int tx = threadIdx.x;
    const int ty = threadIdx.y;

    for (int r = ty; r < 32; r += 8)
        tile[r][tx] = W[(size_t)(k0 + r) * 512 + n0 + tx];
    __syncthreads();

    const float scale = (z == 0) ? 0.04419417382415922f : 1.0f;
    for (int r = ty; r < 32; r += 8) {
        int n = n0 + r;
        int k = k0 + tx;
        float v = tile[tx][r] * scale;
        __nv_bfloat16 hi = __float2bfloat16(v);
        __nv_bfloat16 lo = __float2bfloat16(v - __bfloat162float(hi));
        size_t idx = ((size_t)(z * 512 + n)) * 1024 + k;
        g_Wh[idx] = hi;
        g_Wl[idx] = lo;
    }
}

// ---------------------------------------------------------------------------
// QKV GEMM via mma.sync bf16 split-2, with A-fragment software pipelining.
// ---------------------------------------------------------------------------
#define GB_BUF 40960
#define GB_SMEM (2 * GB_BUF)

__device__ __forceinline__ void gemm_issue(unsigned sb, int buf, int m0, int nbase,
                                           int k0, int tid)
{
    const int lr  = tid >> 1;
    const int lc0 = (tid & 1) * 2;
    unsigned base = sb + buf * GB_BUF;
    const __nv_bfloat16* pa_h = g_Ah + (size_t)(m0 + lr) * 1024 + k0;
    const __nv_bfloat16* pa_l = g_Al + (size_t)(m0 + lr) * 1024 + k0;
    const __nv_bfloat16* pb_h = g_Wh + (size_t)(nbase + lr) * 1024 + k0;
    const __nv_bfloat16* pb_l = g_Wl + (size_t)(nbase + lr) * 1024 + k0;
#pragma unroll
    for (int cc = 0; cc < 2; cc++) {
        int c = lc0 + cc;
        unsigned o = lr * 80 + c * 16;
        cpa16(base + o,          pa_h + c * 8);
        cpa16(base + 10240 + o,  pa_l + c * 8);
        cpa16(base + 20480 + o,  pb_h + c * 8);
        cpa16(base + 30720 + o,  pb_l + c * 8);
    }
    cp_commit();
}

__global__ __launch_bounds__(256, 2)
void qkv_hmma()
{
    extern __shared__ char smem[];
    unsigned sb = smem_u32(smem);
    const int tid  = threadIdx.x;
    const int lane = tid & 31;
    const int w    = tid >> 5;
    const int wm   = w >> 2;
    const int wn   = w & 3;
    const int nbase = blockIdx.x * 128;
    const int m0    = blockIdx.y * 128;

    float acc[4][4][4];
#pragma unroll
    for (int i = 0; i < 4; i++)
#pragma unroll
        for (int j = 0; j < 4; j++)
#pragma unroll
            for (int k = 0; k < 4; k++) acc[i][j][k] = 0.0f;

    const int mrowA = (lane & 7) + ((lane >> 3) & 1) * 8;
    const int kcA   = (lane >> 4) & 1;
    const int nrowB = (lane & 7) + ((lane >> 4) & 1) * 8;
    const int kcB   = (lane >> 3) & 1;
    const unsigned aoff = (wm * 64 + mrowA) * 80 + kcA * 16;
    const unsigned boff = 20480u + (wn * 32 + nrowB) * 80 + kcB * 16;

    gemm_issue(sb, 0, m0, nbase, 0, tid);

    for (int ch = 0; ch < 32; ++ch) {
        if (ch + 1 < 32) {
            gemm_issue(sb, (ch + 1) & 1, m0, nbase, (ch + 1) * 32, tid);
            cp_wait<1>();
        } else {
            cp_wait<0>();
        }
        __syncthreads();

        unsigned base = sb + (ch & 1) * GB_BUF;
#pragma unroll
        for (int ks = 0; ks < 2; ks++) {
            unsigned Bh[8], Bl[8];
            ldsm4(&Bh[0], base + boff + ks * 32);
            ldsm4(&Bh[4], base + boff + 16 * 80 + ks * 32);
            ldsm4(&Bl[0], base + boff + 10240 + ks * 32);
            ldsm4(&Bl[4], base + boff + 10240 + 16 * 80 + ks * 32);
            // software-pipelined A fragments (double-buffered)
            unsigned Ahb[2][4], Alb[2][4];
            ldsm4(Ahb[0], base + aoff + ks * 32);
            ldsm4(Alb[0], base + aoff + 10240 + ks * 32);
#pragma unroll
            for (int mt = 0; mt < 4; mt++) {
                int cur = mt & 1;
                if (mt < 3) {
                    ldsm4(Ahb[cur ^ 1], base + aoff + (mt + 1) * (16 * 80) + ks * 32);
                    ldsm4(Alb[cur ^ 1], base + aoff + 10240 + (mt + 1) * (16 * 80) + ks * 32);
                }
#pragma unroll
                for (int nt = 0; nt < 4; nt++) {
                    mma_bf16(acc[mt][nt], Ahb[cur], Bh[nt * 2], Bh[nt * 2 + 1]);
                    mma_bf16(acc[mt][nt], Ahb[cur], Bl[nt * 2], Bl[nt * 2 + 1]);
                    mma_bf16(acc[mt][nt], Alb[cur], Bh[nt * 2], Bh[nt * 2 + 1]);
                }
            }
        }
        __syncthreads();
    }

    // Epilogue: fp32 acc -> bf16 hi/lo stores
    const int z = nbase >> 9;
    __nv_bfloat16* Xh = (z == 0) ? g_qh : ((z == 1) ? g_kh : g_vh);
    __nv_bfloat16* Xl = (z == 0) ? g_ql : ((z == 1) ? g_kl : g_vl);
    const int colb = (nbase & 511) + wn * 32;
    const int gid = lane >> 2, tig = lane & 3;
#pragma unroll
    for (int mt = 0; mt < 4; mt++) {
#pragma unroll
        for (int nt = 0; nt < 4; nt++) {
            int row = m0 + wm * 64 + mt * 16 + gid;
            int col = colb + nt * 8 + tig * 2;
#pragma unroll
            for (int rr = 0; rr < 2; rr++) {
                float v0 = acc[mt][nt][rr * 2 + 0];
                float v1 = acc[mt][nt][rr * 2 + 1];
                __nv_bfloat16 h0 = __float2bfloat16(v0);
                __nv_bfloat16 h1 = __float2bfloat16(v1);
                __nv_bfloat16 l0 = __float2bfloat16(v0 - __bfloat162float(h0));
                __nv_bfloat16 l1 = __float2bfloat16(v1 - __bfloat162float(h1));
                size_t o = (size_t)(row + rr * 8) * 512 + col;
                *(__nv_bfloat162*)(Xh + o) = __nv_bfloat162(h0, h1);
                *(__nv_bfloat162*)(Xl + o) = __nv_bfloat162(l0, l1);
            }
        }
    }
}

// ---------------------------------------------------------------------------
// Tensor-core flash attention + fused LayerNorm — 2 CTAs/SM, frag pipelining.
// CTA = (b, 32-row q-tile), 256 threads (8 warps), smem 111.3KB => 2 CTAs/SM.
// ---------------------------------------------------------------------------
#define SD 68        // S pitch fp32
#define PP 72        // P pitch bf16 (144B, odd*16B)

#define OQH 0                    /* 32 x 1040B = 33280 */
#define OQL 33280                /* -> 66560 */
#define OCB 66560                /* 2 bufs x 18432 (hi 9216 | lo 9216) -> 103424 */
#define OSP 103424               /* S 32x68 fp32 (8704), overlaid by P (9216) */
#define OPH 103424
#define OPL 108032
#define OAL 112640               /* fp32 32 */
#define OLL 112768               /* fp32 32 */
#define ORS 112896               /* fp32 32x4 */
#define ORQ 113408               /* fp32 32x4 */
#define ATTN_SMEM 113920

#define NEG_INF __int_as_float(0xff800000)

// Load one 64-key x 64-d hi/lo chunk of K or V into buffer `buf`.
__device__ __forceinline__ void attn_load_chunk(unsigned sb, int buf,
                                                const __nv_bfloat16* Xh,
                                                const __nv_bfloat16* Xl,
                                                size_t srow0, int dc, int tid)
{
#pragma unroll
    for (int i = 0; i < 4; i++) {
        int idx = tid + i * 256;          // 0..1023
        int which = idx >> 9;             // 0:hi 1:lo
        int u = idx & 511;
        int row = u >> 3;                 // 0..63 (key)
        int c = u & 7;                    // 16B unit within 64 d (128B)
        const __nv_bfloat16* src = (which ? Xl : Xh) + (srow0 + row) * 512 + dc * 64 + c * 8;
        unsigned dst = sb + OCB + buf * 18432 + which * 9216 + row * 144 + c * 16;
        cpa16(dst, src);
    }
    cp_commit();
}

__global__ __launch_bounds__(256, 2)
void attn_mma(const float* __restrict__ gamma, const float* __restrict__ beta,
              float* __restrict__ out)
{
    extern __shared__ char smc[];
    unsigned sb = smem_u32(smc);
    float* S    = (float*)(smc + OSP);
    float* AL   = (float*)(smc + OAL);
    float* LL   = (float*)(smc + OLL);
    float* RS   = (float*)(smc + ORS);
    float* RQ   = (float*)(smc + ORQ);
    __nv_bfloat16* PH = (__nv_bfloat16*)(smc + OPH);
    __nv_bfloat16* PL = (__nv_bfloat16*)(smc + OPL);

    const int b   = blockIdx.y;
    const int qb  = gridDim.x - 1 - blockIdx.x;     // heavy tiles first
    const int tid = threadIdx.x;
    const int lane = tid & 31;
    const int w    = tid >> 5;      // 0..7
    const int rh   = w >> 2;        // 0..1 (16-row group)
    const int cg   = w & 3;         // S col group (16 cols)
    const int vg   = w & 3;         // PV col group (16 d-cols per chunk)
    const int ti = tid >> 4;        // 0..15 -> rows 2ti, 2ti+1
    const int tj = tid & 15;        // cols 4tj..4tj+3

    const size_t qrow0 = (size_t)b * SEQ + (size_t)qb * 32;

    // --- load Q (32 x 512 hi/lo): 4096 units / 256 = 16 per thread ---
#pragma unroll
    for (int i = 0; i < 16; i++) {
        int idx = tid + i * 256;
        int which = idx >> 11;            // 0:Qh 1:Ql
        int u = idx & 2047;
        int row = u >> 6;                 // 0..31
        int c = u & 63;
        const __nv_bfloat16* src = (which ? g_ql : g_qh) + (qrow0 + row) * 512 + c * 8;
        unsigned dst = sb + (which ? OQL : OQH) + row * 1040 + c * 16;
        cpa16(dst, src);
    }
    cp_commit();

    // PV accumulator: acc[dc][nt][4]
    float acc[8][2][4];
#pragma unroll
    for (int d = 0; d < 8; d++)
#pragma unroll
        for (int nt = 0; nt < 2; nt++)
#pragma unroll
            for (int k = 0; k < 4; k++) acc[d][nt][k] = 0.0f;

    float m0r = NEG_INF, m1r = NEG_INF;
    float l0r = 0.0f,    l1r = 0.0f;

    // ldmatrix lane components
    const unsigned qrow_a = rh * 16 + (lane & 7) + ((lane >> 3) & 1) * 8;
    const unsigned kca    = ((lane >> 4) & 1) * 8;
    const unsigned krow4  = cg * 16 + ((lane >> 4) & 1) * 8 + (lane & 7);
    const unsigned kc4    = ((lane >> 3) & 1) * 8;
    const unsigned prow_a = qrow_a;
    const unsigned psel   = ((lane >> 4) & 1) * 8;
    const unsigned vsrow  = ((lane >> 3) & 1) * 8 + (lane & 7);
    const unsigned vdoff  = ((lane >> 4) & 1) * 8;

    const int jbmax = qb >> 1;   // 64-key tiles; diagonal tile = jbmax

    // prologue: prefetch K d-chunks 0,1 of jb=0
    attn_load_chunk(sb, 0, g_kh, g_kl, (size_t)b * SEQ, 0, tid);
    attn_load_chunk(sb, 1, g_kh, g_kl, (size_t)b * SEQ, 1, tid);

    for (int jb = 0; jb <= jbmax; jb++) {
        const size_t srow0 = (size_t)b * SEQ + (size_t)jb * 64;
        const bool last = (jb == jbmax);

        // ---- S phase: S(32x64) = Q Kt over 8 d-chunks of 64 ----
        float s0a[2][4] = {{0,0,0,0},{0,0,0,0}};   // Ah·Bh + Ah·Bl
        float s1a[2][4] = {{0,0,0,0},{0,0,0,0}};   // Al·Bh
#pragma unroll
        for (int dc = 0; dc < 8; dc++) {
            cp_wait<1>();
            __syncthreads();
            unsigned kb = sb + OCB + (dc & 1) * 18432;
            unsigned qbase = sb + OQH + qrow_a * 1040 + (dc * 64 + kca) * 2;
            unsigned kbase = kb + krow4 * 144 + kc4 * 2;

            // software-pipelined fragment buffers (double-buffered over ks)
            unsigned Qh[2][4], Ql[2][4], Bh[2][4], Bl[2][4];
            ldsm4(Qh[0], qbase);
            ldsm4(Ql[0], qbase + 33280u);
            ldsm4(Bh[0], kbase);
            ldsm4(Bl[0], kbase + 9216u);
#pragma unroll
            for (int ks = 0; ks < 4; ks++) {
                int cur = ks & 1;
                if (ks < 3) {
                    ldsm4(Qh[cur ^ 1], qbase + (ks + 1) * 32);
                    ldsm4(Ql[cur ^ 1], qbase + 33280u + (ks + 1) * 32);
                    ldsm4(Bh[cur ^ 1], kbase + (ks + 1) * 32);
                    ldsm4(Bl[cur ^ 1], kbase + 9216u + (ks + 1) * 32);
                }
                mma_bf16(s0a[0], Qh[cur], Bh[cur][0], Bh[cur][1]);
                mma_bf16(s0a[1], Qh[cur], Bh[cur][2], Bh[cur][3]);
                mma_bf16(s1a[0], Ql[cur], Bh[cur][0], Bh[cur][1]);
                mma_bf16(s1a[1], Ql[cur], Bh[cur][2], Bh[cur][3]);
                mma_bf16(s0a[0], Qh[cur], Bl[cur][0], Bl[cur][1]);
                mma_bf16(s0a[1], Qh[cur], Bl[cur][2], Bl[cur][3]);
            }
            if (dc == 7) {
                int r  = lane >> 2;
                int c2 = (lane & 3) * 2;
                int row0 = rh * 16 + r;
#pragma unroll
                for (int nt2 = 0; nt2 < 2; nt2++) {
                    int col = cg * 16 + nt2 * 8 + c2;
                    *(float2*)&S[row0 * SD + col] =
                        make_float2(s0a[nt2][0] + s1a[nt2][0], s0a[nt2][1] + s1a[nt2][1]);
                    *(float2*)&S[(row0 + 8) * SD + col] =
                        make_float2(s0a[nt2][2] + s1a[nt2][2], s0a[nt2][3] + s1a[nt2][3]);
                }
            }
            __syncthreads();
            if (dc < 6)
                attn_load_chunk(sb, dc & 1, g_kh, g_kl, srow0, dc + 2, tid);
            else
                attn_load_chunk(sb, dc & 1, g_vh, g_vl, srow0, dc - 6, tid);
        }

        // ---- softmax (each thread: rows 2ti,2ti+1 x cols 4tj..4tj+3) ----
        {
            float4 v0 = *(float4*)&S[(2 * ti) * SD + 4 * tj];
            float4 v1 = *(float4*)&S[(2 * ti + 1) * SD + 4 * tj];
            float a0[4] = {v0.x, v0.y, v0.z, v0.w};
            float a1[4] = {v1.x, v1.y, v1.z, v1.w};

            if (jb == jbmax) {
                int qi0 = qb * 32 + 2 * ti;
                int kj  = jb * 64 + 4 * tj;
#pragma unroll
                for (int c = 0; c < 4; c++) {
                    if (kj + c > qi0)     a0[c] = NEG_INF;
                    if (kj + c > qi0 + 1) a1[c] = NEG_INF;
                }
            }

            float r0 = fmaxf(fmaxf(a0[0], a0[1]), fmaxf(a0[2], a0[3]));
            float r1 = fmaxf(fmaxf(a1[0], a1[1]), fmaxf(a1[2], a1[3]));
#pragma unroll
            for (int off = 1; off < 16; off <<= 1) {
                r0 = fmaxf(r0, __shfl_xor_sync(0xffffffffu, r0, off));
                r1 = fmaxf(r1, __shfl_xor_sync(0xffffffffu, r1, off));
            }
            float mn0 = fmaxf(m0r, r0);
            float mn1 = fmaxf(m1r, r1);
            float al0 = __expf(m0r - mn0);
            float al1 = __expf(m1r - mn1);

            float p0[4], p1[4];
#pragma unroll
            for (int c = 0; c < 4; c++) {
                p0[c] = __expf(a0[c] - mn0);
                p1[c] = __expf(a1[c] - mn1);
            }
            float rs0 = (p0[0] + p0[1]) + (p0[2] + p0[3]);
            float rs1 = (p1[0] + p1[1]) + (p1[2] + p1[3]);
#pragma unroll
            for (int off = 1; off < 16; off <<= 1) {
                rs0 += __shfl_xor_sync(0xffffffffu, rs0, off);
                rs1 += __shfl_xor_sync(0xffffffffu, rs1, off);
            }
            l0r = al0 * l0r + rs0;  m0r = mn0;
            l1r = al1 * l1r + rs1;  m1r = mn1;

            if (tj == 0) {
                AL[2 * ti]     = al0;
                AL[2 * ti + 1] = al1;
                LL[2 * ti]     = l0r;
                LL[2 * ti + 1] = l1r;
            }
            __syncthreads();   // all S reads done before P overlays S

            __nv_bfloat16 h0[4], h1[4];
#pragma unroll
            for (int c = 0; c < 4; c++) {
                h0[c] = __float2bfloat16(p0[c]);
                h1[c] = __float2bfloat16(p1[c]);
            }
            *(__nv_bfloat162*)&PH[(2 * ti) * PP + 4 * tj]         = __nv_bfloat162(h0[0], h0[1]);
            *(__nv_bfloat162*)&PH[(2 * ti) * PP + 4 * tj + 2]     = __nv_bfloat162(h0[2], h0[3]);
            *(__nv_bfloat162*)&PH[(2 * ti + 1) * PP + 4 * tj]     = __nv_bfloat162(h1[0], h1[1]);
            *(__nv_bfloat162*)&PH[(2 * ti + 1) * PP + 4 * tj + 2] = __nv_bfloat162(h1[2], h1[3]);
            *(__nv_bfloat162*)&PL[(2 * ti) * PP + 4 * tj] = __nv_bfloat162(
                __float2bfloat16(p0[0] - __bfloat162float(h0[0])),
                __float2bfloat16(p0[1] - __bfloat162float(h0[1])));
            *(__nv_bfloat162*)&PL[(2 * ti) * PP + 4 * tj + 2] = __nv_bfloat162(
                __float2bfloat16(p0[2] - __bfloat162float(h0[2])),
                __float2bfloat16(p0[3] - __bfloat162float(h0[3])));
            *(__nv_bfloat162*)&PL[(2 * ti + 1) * PP + 4 * tj] = __nv_bfloat162(
                __float2bfloat16(p1[0] - __bfloat162float(h1[0])),
                __float2bfloat16(p1[1] - __bfloat162float(h1[1])));
            *(__nv_bfloat162*)&PL[(2 * ti + 1) * PP + 4 * tj + 2] = __nv_bfloat162(
                __float2bfloat16(p1[2] - __bfloat162float(h1[2])),
                __float2bfloat16(p1[3] - __bfloat162float(h1[3])));
        }
        __syncthreads();   // P + AL visible

        // hoist P fragments (whole 64-key tile) into registers
        unsigned Phf[4][4], Plf[4][4];
#pragma unroll
        for (int ks2 = 0; ks2 < 4; ks2++) {
            unsigned pcol = (ks2 * 16 + psel) * 2;
            ldsm4(Phf[ks2], sb + OPH + prow_a * 144 + pcol);
            ldsm4(Plf[ks2], sb + OPL + prow_a * 144 + pcol);
        }

        // scale accumulators by alpha
        {
            float a0 = AL[rh * 16 + (lane >> 2)];
            float a1 = AL[rh * 16 + (lane >> 2) + 8];
#pragma unroll
            for (int d = 0; d < 8; d++)
#pragma unroll
                for (int nt = 0; nt < 2; nt++) {
                    acc[d][nt][0] *= a0; acc[d][nt][1] *= a0;
                    acc[d][nt][2] *= a1; acc[d][nt][3] *= a1;
                }
        }

        // ---- PV phase over 8 streamed V d-chunks (V frags pipelined) ----
#pragma unroll
        for (int dc = 0; dc < 8; dc++) {
            if (last && dc == 7) cp_wait<0>(); else cp_wait<1>();
            __syncthreads();
            unsigned vb = sb + OCB + (dc & 1) * 18432;
            unsigned vbase = vb + vsrow * 144 + (vg * 16 + vdoff) * 2;

            unsigned Vh[2][4], Vl[2][4];
            ldsm4t(Vh[0], vbase);
            ldsm4t(Vl[0], vbase + 9216u);
#pragma unroll
            for (int ks2 = 0; ks2 < 4; ks2++) {
                int cur = ks2 & 1;
                if (ks2 < 3) {
                    ldsm4t(Vh[cur ^ 1], vbase + (ks2 + 1) * (16 * 144));
                    ldsm4t(Vl[cur ^ 1], vbase + 9216u + (ks2 + 1) * (16 * 144));
                }
                mma_bf16(acc[dc][0], Phf[ks2], Vh[cur][0], Vh[cur][1]);
                mma_bf16(acc[dc][0], Plf[ks2], Vh[cur][0], Vh[cur][1]);
                mma_bf16(acc[dc][0], Phf[ks2], Vl[cur][0], Vl[cur][1]);
                mma_bf16(acc[dc][1], Phf[ks2], Vh[cur][2], Vh[cur][3]);
                mma_bf16(acc[dc][1], Plf[ks2], Vh[cur][2], Vh[cur][3]);
                mma_bf16(acc[dc][1], Phf[ks2], Vl[cur][2], Vl[cur][3]);
            }
            __syncthreads();
            if (dc < 6)
                attn_load_chunk(sb, dc & 1, g_vh, g_vl, srow0, dc + 2, tid);
            else if (!last)
                attn_load_chunk(sb, dc & 1, g_kh, g_kl, srow0 + 64, dc - 6, tid);
        }
    }

    // ---- epilogue: 1/l, LayerNorm, store ----
    {
        int r  = lane >> 2;
        int c2 = (lane & 3) * 2;
        int row0 = rh * 16 + r;
        int row1 = row0 + 8;
        float linv0 = 1.0f / LL[row0];
        float linv1 = 1.0f / LL[row1];
        float s0 = 0.f, q0 = 0.f, s1 = 0.f, q1 = 0.f;
#pragma unroll
        for (int d = 0; d < 8; d++)
#pragma unroll
            for (int nt = 0; nt < 2; nt++) {
                acc[d][nt][0] *= linv0; acc[d][nt][1] *= linv0;
                acc[d][nt][2] *= linv1; acc[d][nt][3] *= linv1;
                s0 += acc[d][nt][0] + acc[d][nt][1];
                q0 += acc[d][nt][0] * acc[d][nt][0] + acc[d][nt][1] * acc[d][nt][1];
                s1 += acc[d][nt][2] + acc[d][nt][3];
                q1 += acc[d][nt][2] * acc[d][nt][2] + acc[d][nt][3] * acc[d][nt][3];
            }
#pragma unroll
        for (int off = 1; off < 4; off <<= 1) {
            s0 += __shfl_xor_sync(0xffffffffu, s0, off);
            q0 += __shfl_xor_sync(0xffffffffu, q0, off);
            s1 += __shfl_xor_sync(0xffffffffu, s1, off);
            q1 += __shfl_xor_sync(0xffffffffu, q1, off);
        }
        if ((lane & 3) == 0) {
            RS[row0 * 4 + vg] = s0;  RQ[row0 * 4 + vg] = q0;
            RS[row1 * 4 + vg] = s1;  RQ[row1 * 4 + vg] = q1;
        }
        __syncthreads();
        float ts0 = RS[row0 * 4] + RS[row0 * 4 + 1] + RS[row0 * 4 + 2] + RS[row0 * 4 + 3];
        float tq0 = RQ[row0 * 4] + RQ[row0 * 4 + 1] + RQ[row0 * 4 + 2] + RQ[row0 * 4 + 3];
        float ts1 = RS[row1 * 4] + RS[row1 * 4 + 1] + RS[row1 * 4 + 2] + RS[row1 * 4 + 3];
        float tq1 = RQ[row1 * 4] + RQ[row1 * 4 + 1] + RQ[row1 * 4 + 2] + RQ[row1 * 4 + 3];
        const float invD = 1.0f / (float)DIM;
        float mu0 = ts0 * invD, var0 = tq0 * invD - mu0 * mu0;
        float mu1 = ts1 * invD, var1 = tq1 * invD - mu1 * mu1;
        float rstd0 = rsqrtf(var0 + 1e-5f);
        float rstd1 = rsqrtf(var1 + 1e-5f);

        size_t ob0 = (qrow0 + row0) * 512;
        size_t ob1 = (qrow0 + row1) * 512;
#pragma unroll
        for (int d = 0; d < 8; d++)
#pragma unroll
            for (int nt = 0; nt < 2; nt++) {
                int col = d * 64 + vg * 16 + nt * 8 + c2;
                float g0 = gamma[col], g1 = gamma[col + 1];
                float be0 = beta[col], be1 = beta[col + 1];
                float2 o0 = make_float2((acc[d][nt][0] - mu0) * rstd0 * g0 + be0,
                                        (acc[d][nt][1] - mu0) * rstd0 * g1 + be1);
                float2 o1 = make_float2((acc[d][nt][2] - mu1) * rstd1 * g0 + be0,
                                        (acc[d][nt][3] - mu1) * rstd1 * g1 + be1);
                *(float2*)(out + ob0 + col) = o0;
                *(float2*)(out + ob1 + col) = o1;
            }
    }
}

// ---------------------------------------------------------------------------
// Launch
// ---------------------------------------------------------------------------
extern "C" void kernel_launch(void* const* d_in, const int* in_sizes, int n_in,
                              void* d_out, int out_size)
{
    const float* x0    = (const float*)d_in[0];
    const float* x1    = (const float*)d_in[1];
    const float* Wq    = (const float*)d_in[2];
    const float* Wk    = (const float*)d_in[3];
    const float* Wv    = (const float*)d_in[4];
    const float* gamma = (const float*)d_in[5];
    const float* beta  = (const float*)d_in[6];
    float* out = (float*)d_out;

    cudaFuncSetAttribute(qkv_hmma, cudaFuncAttributeMaxDynamicSharedMemorySize, GB_SMEM);
    cudaFuncSetAttribute(attn_mma, cudaFuncAttributeMaxDynamicSharedMemorySize, ATTN_SMEM);

    conv_x<<<MTOT, 256>>>(x0, x1);
    conv_w<<<dim3(16, 32, 3), dim3(32, 8)>>>(Wq, Wk, Wv);
    qkv_hmma<<<dim3(12, 128), 256, GB_SMEM>>>();
    attn_mma<<<dim3(SEQ / 32, BATCH), 256, ATTN_SMEM>>>(gamma, beta, out);
}

// round 11
// speedup vs baseline: 1.0082x; 1.0082x over previous
#include <cuda_runtime.h>
#include <cuda_bf16.h>
#include <math.h>

// Problem constants
#define BATCH 8
#define SEQ   2048
#define DIM   512
#define KDIM  1024
#define MTOT  (BATCH*SEQ)   // 16384

// Scratch (no cudaMalloc allowed)
__device__ __nv_bfloat16 g_Ah[(size_t)MTOT * KDIM];
__device__ __nv_bfloat16 g_Al[(size_t)MTOT * KDIM];
__device__ __nv_bfloat16 g_Wh[(size_t)3 * DIM * KDIM];
__device__ __nv_bfloat16 g_Wl[(size_t)3 * DIM * KDIM];
__device__ __nv_bfloat16 g_qh[(size_t)MTOT * DIM];
__device__ __nv_bfloat16 g_ql[(size_t)MTOT * DIM];
__device__ __nv_bfloat16 g_kh[(size_t)MTOT * DIM];
__device__ __nv_bfloat16 g_kl[(size_t)MTOT * DIM];
__device__ __nv_bfloat16 g_vh[(size_t)MTOT * DIM];
__device__ __nv_bfloat16 g_vl[(size_t)MTOT * DIM];

// ---------------------------------------------------------------------------
// helpers
// ---------------------------------------------------------------------------
__device__ __forceinline__ unsigned smem_u32(const void* p) {
    unsigned a;
    asm("{ .reg .u64 t; cvta.to.shared.u64 t, %1; cvt.u32.u64 %0, t; }" : "=r"(a) : "l"(p));
    return a;
}
__device__ __forceinline__ void cpa16(unsigned dst, const void* src) {
    asm volatile("cp.async.cg.shared.global [%0], [%1], 16;"
                 :: "r"(dst), "l"(__cvta_generic_to_global(src)) : "memory");
}
__device__ __forceinline__ void cp_commit() {
    asm volatile("cp.async.commit_group;" ::: "memory");
}
template <int N>
__device__ __forceinline__ void cp_wait() {
    asm volatile("cp.async.wait_group %0;" :: "n"(N) : "memory");
}
__device__ __forceinline__ void ldsm4(unsigned* r, unsigned addr) {
    asm volatile("ldmatrix.sync.aligned.m8n8.x4.shared.b16 {%0,%1,%2,%3}, [%4];"
                 : "=r"(r[0]), "=r"(r[1]), "=r"(r[2]), "=r"(r[3]) : "r"(addr));
}
__device__ __forceinline__ void ldsm4t(unsigned* r, unsigned addr) {
    asm volatile("ldmatrix.sync.aligned.m8n8.x4.trans.shared.b16 {%0,%1,%2,%3}, [%4];"
                 : "=r"(r[0]), "=r"(r[1]), "=r"(r[2]), "=r"(r[3]) : "r"(addr));
}
__device__ __forceinline__ void mma_bf16(float* c, const unsigned* a,
                                         unsigned b0, unsigned b1) {
    asm volatile(
        "mma.sync.aligned.m16n8k16.row.col.f32.bf16.bf16.f32 "
        "{%0,%1,%2,%3}, {%4,%5,%6,%7}, {%8,%9}, {%0,%1,%2,%3};"
        : "+f"(c[0]), "+f"(c[1]), "+f"(c[2]), "+f"(c[3])
        : "r"(a[0]), "r"(a[1]), "r"(a[2]), "r"(a[3]), "r"(b0), "r"(b1));
}

// ---------------------------------------------------------------------------
// Conversion: x0|x1 -> bf16 hi/lo, row-major [MTOT][1024]
// ---------------------------------------------------------------------------
__global__ __launch_bounds__(256)
void conv_x(const float* __restrict__ x0, const float* __restrict__ x1)
{
    unsigned t = blockIdx.x * 256u + threadIdx.x;
    unsigned m  = t >> 8;
    unsigned k4 = (t & 255u) * 4u;
    float4 v = (k4 < 512u)
        ? *(const float4*)(x0 + (size_t)m * 512 + k4)
        : *(const float4*)(x1 + (size_t)m * 512 + (k4 - 512u));
    __nv_bfloat16 h0 = __float2bfloat16(v.x);
    __nv_bfloat16 h1 = __float2bfloat16(v.y);
    __nv_bfloat16 h2 = __float2bfloat16(v.z);
    __nv_bfloat16 h3 = __float2bfloat16(v.w);
    __nv_bfloat16 l0 = __float2bfloat16(v.x - __bfloat162float(h0));
    __nv_bfloat16 l1 = __float2bfloat16(v.y - __bfloat162float(h1));
    __nv_bfloat16 l2 = __float2bfloat16(v.z - __bfloat162float(h2));
    __nv_bfloat16 l3 = __float2bfloat16(v.w - __bfloat162float(h3));
    size_t o = (size_t)m * 1024 + k4;
    __nv_bfloat162* dh = (__nv_bfloat162*)(g_Ah + o);
    __nv_bfloat162* dl = (__nv_bfloat162*)(g_Al + o);
    dh[0] = __nv_bfloat162(h0, h1); dh[1] = __nv_bfloat162(h2, h3);
    dl[0] = __nv_bfloat162(l0, l1); dl[1] = __nv_bfloat162(l2, l3);
}

// ---------------------------------------------------------------------------
// W[k][n] -> W^T hi/lo bf16, n-major rows (q scaled by 1/sqrt(D))
// ---------------------------------------------------------------------------
__global__ __launch_bounds__(256)
void conv_w(const float* __restrict__ Wq, const float* __restrict__ Wk,
            const float* __restrict__ Wv)
{
    __shared__ float tile[32][33];
    const int z  = blockIdx.z;
    const float* __restrict__ W = (z == 0) ? Wq : ((z == 1) ? Wk : Wv);
    const int n0 = blockIdx.x * 32;
    const int k0 = blockIdx.y * 32;
    const int tx = threadIdx.x;
    const int ty = threadIdx.y;

    for (int r = ty; r < 32; r += 8)
        tile[r][tx] = W[(size_t)(k0 + r) * 512 + n0 + tx];
    __syncthreads();

    const float scale = (z == 0) ? 0.04419417382415922f : 1.0f;
    for (int r = ty; r < 32; r += 8) {
        int n = n0 + r;
        int k = k0 + tx;
        float v = tile[tx][r] * scale;
        __nv_bfloat16 hi = __float2bfloat16(v);
        __nv_bfloat16 lo = __float2bfloat16(v - __bfloat162float(hi));
        size_t idx = ((size_t)(z * 512 + n)) * 1024 + k;
        g_Wh[idx] = hi;
        g_Wl[idx] = lo;
    }
}

// ---------------------------------------------------------------------------
// QKV GEMM via mma.sync bf16 split-2, with A-fragment software pipelining.
// (kept from R10 — measured ~20us better than unpipelined)
// ---------------------------------------------------------------------------
#define GB_BUF 40960
#define GB_SMEM (2 * GB_BUF)

__device__ __forceinline__ void gemm_issue(unsigned sb, int buf, int m0, int nbase,
                                           int k0, int tid)
{
    const int lr  = tid >> 1;
    const int lc0 = (tid & 1) * 2;
    unsigned base = sb + buf * GB_BUF;
    const __nv_bfloat16* pa_h = g_Ah + (size_t)(m0 + lr) * 1024 + k0;
    const __nv_bfloat16* pa_l = g_Al + (size_t)(m0 + lr) * 1024 + k0;
    const __nv_bfloat16* pb_h = g_Wh + (size_t)(nbase + lr) * 1024 + k0;
    const __nv_bfloat16* pb_l = g_Wl + (size_t)(nbase + lr) * 1024 + k0;
#pragma unroll
    for (int cc = 0; cc < 2; cc++) {
        int c = lc0 + cc;
        unsigned o = lr * 80 + c * 16;
        cpa16(base + o,          pa_h + c * 8);
        cpa16(base + 10240 + o,  pa_l + c * 8);
        cpa16(base + 20480 + o,  pb_h + c * 8);
        cpa16(base + 30720 + o,  pb_l + c * 8);
    }
    cp_commit();
}

__global__ __launch_bounds__(256, 2)
void qkv_hmma()
{
    extern __shared__ char smem[];
    unsigned sb = smem_u32(smem);
    const int tid  = threadIdx.x;
    const int lane = tid & 31;
    const int w    = tid >> 5;
    const int wm   = w >> 2;
    const int wn   = w & 3;
    const int nbase = blockIdx.x * 128;
    const int m0    = blockIdx.y * 128;

    float acc[4][4][4];
#pragma unroll
    for (int i = 0; i < 4; i++)
#pragma unroll
        for (int j = 0; j < 4; j++)
#pragma unroll
            for (int k = 0; k < 4; k++) acc[i][j][k] = 0.0f;

    const int mrowA = (lane & 7) + ((lane >> 3) & 1) * 8;
    const int kcA   = (lane >> 4) & 1;
    const int nrowB = (lane & 7) + ((lane >> 4) & 1) * 8;
    const int kcB   = (lane >> 3) & 1;
    const unsigned aoff = (wm * 64 + mrowA) * 80 + kcA * 16;
    const unsigned boff = 20480u + (wn * 32 + nrowB) * 80 + kcB * 16;

    gemm_issue(sb, 0, m0, nbase, 0, tid);

    for (int ch = 0; ch < 32; ++ch) {
        if (ch + 1 < 32) {
            gemm_issue(sb, (ch + 1) & 1, m0, nbase, (ch + 1) * 32, tid);
            cp_wait<1>();
        } else {
            cp_wait<0>();
        }
        __syncthreads();

        unsigned base = sb + (ch & 1) * GB_BUF;
#pragma unroll
        for (int ks = 0; ks < 2; ks++) {
            unsigned Bh[8], Bl[8];
            ldsm4(&Bh[0], base + boff + ks * 32);
            ldsm4(&Bh[4], base + boff + 16 * 80 + ks * 32);
            ldsm4(&Bl[0], base + boff + 10240 + ks * 32);
            ldsm4(&Bl[4], base + boff + 10240 + 16 * 80 + ks * 32);
            // software-pipelined A fragments (double-buffered)
            unsigned Ahb[2][4], Alb[2][4];
            ldsm4(Ahb[0], base + aoff + ks * 32);
            ldsm4(Alb[0], base + aoff + 10240 + ks * 32);
#pragma unroll
            for (int mt = 0; mt < 4; mt++) {
                int cur = mt & 1;
                if (mt < 3) {
                    ldsm4(Ahb[cur ^ 1], base + aoff + (mt + 1) * (16 * 80) + ks * 32);
                    ldsm4(Alb[cur ^ 1], base + aoff + 10240 + (mt + 1) * (16 * 80) + ks * 32);
                }
#pragma unroll
                for (int nt = 0; nt < 4; nt++) {
                    mma_bf16(acc[mt][nt], Ahb[cur], Bh[nt * 2], Bh[nt * 2 + 1]);
                    mma_bf16(acc[mt][nt], Ahb[cur], Bl[nt * 2], Bl[nt * 2 + 1]);
                    mma_bf16(acc[mt][nt], Alb[cur], Bh[nt * 2], Bh[nt * 2 + 1]);
                }
            }
        }
        __syncthreads();
    }

    // Epilogue: fp32 acc -> bf16 hi/lo stores
    const int z = nbase >> 9;
    __nv_bfloat16* Xh = (z == 0) ? g_qh : ((z == 1) ? g_kh : g_vh);
    __nv_bfloat16* Xl = (z == 0) ? g_ql : ((z == 1) ? g_kl : g_vl);
    const int colb = (nbase & 511) + wn * 32;
    const int gid = lane >> 2, tig = lane & 3;
#pragma unroll
    for (int mt = 0; mt < 4; mt++) {
#pragma unroll
        for (int nt = 0; nt < 4; nt++) {
            int row = m0 + wm * 64 + mt * 16 + gid;
            int col = colb + nt * 8 + tig * 2;
#pragma unroll
            for (int rr = 0; rr < 2; rr++) {
                float v0 = acc[mt][nt][rr * 2 + 0];
                float v1 = acc[mt][nt][rr * 2 + 1];
                __nv_bfloat16 h0 = __float2bfloat16(v0);
                __nv_bfloat16 h1 = __float2bfloat16(v1);
                __nv_bfloat16 l0 = __float2bfloat16(v0 - __bfloat162float(h0));
                __nv_bfloat16 l1 = __float2bfloat16(v1 - __bfloat162float(h1));
                size_t o = (size_t)(row + rr * 8) * 512 + col;
                *(__nv_bfloat162*)(Xh + o) = __nv_bfloat162(h0, h1);
                *(__nv_bfloat162*)(Xl + o) = __nv_bfloat162(l0, l1);
            }
        }
    }
}

// ---------------------------------------------------------------------------
// Tensor-core flash attention + fused LayerNorm — 2 CTAs/SM (R9-exact loops).
// CTA = (b, 32-row q-tile), 256 threads (8 warps), smem 111.3KB => 2 CTAs/SM.
// ---------------------------------------------------------------------------
#define SD 68        // S pitch fp32
#define PP 72        // P pitch bf16 (144B, odd*16B)

#define OQH 0                    /* 32 x 1040B = 33280 */
#define OQL 33280                /* -> 66560 */
#define OCB 66560                /* 2 bufs x 18432 (hi 9216 | lo 9216) -> 103424 */
#define OSP 103424               /* S 32x68 fp32 (8704), overlaid by P (9216) */
#define OPH 103424
#define OPL 108032
#define OAL 112640               /* fp32 32 */
#define OLL 112768               /* fp32 32 */
#define ORS 112896               /* fp32 32x4 */
#define ORQ 113408               /* fp32 32x4 */
#define ATTN_SMEM 113920

#define NEG_INF __int_as_float(0xff800000)

// Load one 64-key x 64-d hi/lo chunk of K or V into buffer `buf`.
__device__ __forceinline__ void attn_load_chunk(unsigned sb, int buf,
                                                const __nv_bfloat16* Xh,
                                                const __nv_bfloat16* Xl,
                                                size_t srow0, int dc, int tid)
{
#pragma unroll
    for (int i = 0; i < 4; i++) {
        int idx = tid + i * 256;          // 0..1023
        int which = idx >> 9;             // 0:hi 1:lo
        int u = idx & 511;
        int row = u >> 3;                 // 0..63 (key)
        int c = u & 7;                    // 16B unit within 64 d (128B)
        const __nv_bfloat16* src = (which ? Xl : Xh) + (srow0 + row) * 512 + dc * 64 + c * 8;
        unsigned dst = sb + OCB + buf * 18432 + which * 9216 + row * 144 + c * 16;
        cpa16(dst, src);
    }
    cp_commit();
}

__global__ __launch_bounds__(256, 2)
void attn_mma(const float* __restrict__ gamma, const float* __restrict__ beta,
              float* __restrict__ out)
{
    extern __shared__ char smc[];
    unsigned sb = smem_u32(smc);
    float* S    = (float*)(smc + OSP);
    float* AL   = (float*)(smc + OAL);
    float* LL   = (float*)(smc + OLL);
    float* RS   = (float*)(smc + ORS);
    float* RQ   = (float*)(smc + ORQ);
    __nv_bfloat16* PH = (__nv_bfloat16*)(smc + OPH);
    __nv_bfloat16* PL = (__nv_bfloat16*)(smc + OPL);

    const int b   = blockIdx.y;
    const int qb  = gridDim.x - 1 - blockIdx.x;     // heavy tiles first
    const int tid = threadIdx.x;
    const int lane = tid & 31;
    const int w    = tid >> 5;      // 0..7
    const int rh   = w >> 2;        // 0..1 (16-row group)
    const int cg   = w & 3;         // S col group (16 cols)
    const int vg   = w & 3;         // PV col group (16 d-cols per chunk)
    const int ti = tid >> 4;        // 0..15 -> rows 2ti, 2ti+1
    const int tj = tid & 15;        // cols 4tj..4tj+3

    const size_t qrow0 = (size_t)b * SEQ + (size_t)qb * 32;

    // --- load Q (32 x 512 hi/lo): 4096 units / 256 = 16 per thread ---
#pragma unroll
    for (int i = 0; i < 16; i++) {
        int idx = tid + i * 256;
        int which = idx >> 11;            // 0:Qh 1:Ql
        int u = idx & 2047;
        int row = u >> 6;                 // 0..31
        int c = u & 63;
        const __nv_bfloat16* src = (which ? g_ql : g_qh) + (qrow0 + row) * 512 + c * 8;
        unsigned dst = sb + (which ? OQL : OQH) + row * 1040 + c * 16;
        cpa16(dst, src);
    }
    cp_commit();

    // PV accumulator: acc[dc][nt][4] — 16 rows x (dc*64 + vg*16 + nt*8) cols
    float acc[8][2][4];
#pragma unroll
    for (int d = 0; d < 8; d++)
#pragma unroll
        for (int nt = 0; nt < 2; nt++)
#pragma unroll
            for (int k = 0; k < 4; k++) acc[d][nt][k] = 0.0f;

    float m0r = NEG_INF, m1r = NEG_INF;
    float l0r = 0.0f,    l1r = 0.0f;

    // ldmatrix lane components
    const unsigned qrow_a = rh * 16 + (lane & 7) + ((lane >> 3) & 1) * 8;
    const unsigned kca    = ((lane >> 4) & 1) * 8;
    const unsigned krow4  = cg * 16 + ((lane >> 4) & 1) * 8 + (lane & 7);
    const unsigned kc4    = ((lane >> 3) & 1) * 8;
    const unsigned prow_a = qrow_a;
    const unsigned psel   = ((lane >> 4) & 1) * 8;
    const unsigned vsrow  = ((lane >> 3) & 1) * 8 + (lane & 7);
    const unsigned vdoff  = ((lane >> 4) & 1) * 8;

    const int jbmax = qb >> 1;   // 64-key tiles; diagonal tile = jbmax

    // prologue: prefetch K d-chunks 0,1 of jb=0
    attn_load_chunk(sb, 0, g_kh, g_kl, (size_t)b * SEQ, 0, tid);
    attn_load_chunk(sb, 1, g_kh, g_kl, (size_t)b * SEQ, 1, tid);

    for (int jb = 0; jb <= jbmax; jb++) {
        const size_t srow0 = (size_t)b * SEQ + (size_t)jb * 64;
        const bool last = (jb == jbmax);

        // ---- S phase: S(32x64) = Q Kt over 8 d-chunks of 64 ----
        float s0a[2][4] = {{0,0,0,0},{0,0,0,0}};   // Ah·Bh + Ah·Bl
        float s1a[2][4] = {{0,0,0,0},{0,0,0,0}};   // Al·Bh
#pragma unroll
        for (int dc = 0; dc < 8; dc++) {
            cp_wait<1>();
            __syncthreads();
            unsigned kb = sb + OCB + (dc & 1) * 18432;
#pragma unroll
            for (int ks = 0; ks < 4; ks++) {
                unsigned qcol = (dc * 64 + ks * 16 + kca) * 2;
                unsigned Ah[4], Alo[4], Bh4[4], Bl4[4];
                ldsm4(Ah,  sb + OQH + qrow_a * 1040 + qcol);
                ldsm4(Alo, sb + OQL + qrow_a * 1040 + qcol);
                unsigned kcol = (ks * 16 + kc4) * 2;
                ldsm4(Bh4, kb + krow4 * 144 + kcol);
                ldsm4(Bl4, kb + 9216 + krow4 * 144 + kcol);
                mma_bf16(s0a[0], Ah,  Bh4[0], Bh4[1]);
                mma_bf16(s0a[1], Ah,  Bh4[2], Bh4[3]);
                mma_bf16(s1a[0], Alo, Bh4[0], Bh4[1]);
                mma_bf16(s1a[1], Alo, Bh4[2], Bh4[3]);
                mma_bf16(s0a[0], Ah,  Bl4[0], Bl4[1]);
                mma_bf16(s0a[1], Ah,  Bl4[2], Bl4[3]);
            }
            if (dc == 7) {
                int r  = lane >> 2;
                int c2 = (lane & 3) * 2;
                int row0 = rh * 16 + r;
#pragma unroll
                for (int nt2 = 0; nt2 < 2; nt2++) {
                    int col = cg * 16 + nt2 * 8 + c2;
                    *(float2*)&S[row0 * SD + col] =
                        make_float2(s0a[nt2][0] + s1a[nt2][0], s0a[nt2][1] + s1a[nt2][1]);
                    *(float2*)&S[(row0 + 8) * SD + col] =
                        make_float2(s0a[nt2][2] + s1a[nt2][2], s0a[nt2][3] + s1a[nt2][3]);
                }
            }
            __syncthreads();
            if (dc < 6)
                attn_load_chunk(sb, dc & 1, g_kh, g_kl, srow0, dc + 2, tid);
            else
                attn_load_chunk(sb, dc & 1, g_vh, g_vl, srow0, dc - 6, tid);
        }

        // ---- softmax (each thread: rows 2ti,2ti+1 x cols 4tj..4tj+3) ----
        {
            float4 v0 = *(float4*)&S[(2 * ti) * SD + 4 * tj];
            float4 v1 = *(float4*)&S[(2 * ti + 1) * SD + 4 * tj];
            float a0[4] = {v0.x, v0.y, v0.z, v0.w};
            float a1[4] = {v1.x, v1.y, v1.z, v1.w};

            if (jb == jbmax) {
                int qi0 = qb * 32 + 2 * ti;
                int kj  = jb * 64 + 4 * tj;
#pragma unroll
                for (int c = 0; c < 4; c++) {
                    if (kj + c > qi0)     a0[c] = NEG_INF;
                    if (kj + c > qi0 + 1) a1[c] = NEG_INF;
                }
            }

            float r0 = fmaxf(fmaxf(a0[0], a0[1]), fmaxf(a0[2], a0[3]));
            float r1 = fmaxf(fmaxf(a1[0], a1[1]), fmaxf(a1[2], a1[3]));
#pragma unroll
            for (int off = 1; off < 16; off <<= 1) {
                r0 = fmaxf(r0, __shfl_xor_sync(0xffffffffu, r0, off));
                r1 = fmaxf(r1, __shfl_xor_sync(0xffffffffu, r1, off));
            }
            float mn0 = fmaxf(m0r, r0);
            float mn1 = fmaxf(m1r, r1);
            float al0 = __expf(m0r - mn0);
            float al1 = __expf(m1r - mn1);

            float p0[4], p1[4];
#pragma unroll
            for (int c = 0; c < 4; c++) {
                p0[c] = __expf(a0[c] - mn0);
                p1[c] = __expf(a1[c] - mn1);
            }
            float rs0 = (p0[0] + p0[1]) + (p0[2] + p0[3]);
            float rs1 = (p1[0] + p1[1]) + (p1[2] + p1[3]);
#pragma unroll
            for (int off = 1; off < 16; off <<= 1) {
                rs0 += __shfl_xor_sync(0xffffffffu, rs0, off);
                rs1 += __shfl_xor_sync(0xffffffffu, rs1, off);
            }
            l0r = al0 * l0r + rs0;  m0r = mn0;
            l1r = al1 * l1r + rs1;  m1r = mn1;

            if (tj == 0) {
                AL[2 * ti]     = al0;
                AL[2 * ti + 1] = al1;
                LL[2 * ti]     = l0r;
                LL[2 * ti + 1] = l1r;
            }
            __syncthreads();   // all S reads done before P overlays S

            __nv_bfloat16 h0[4], h1[4];
#pragma unroll
            for (int c = 0; c < 4; c++) {
                h0[c] = __float2bfloat16(p0[c]);
                h1[c] = __float2bfloat16(p1[c]);
            }
            *(__nv_bfloat162*)&PH[(2 * ti) * PP + 4 * tj]         = __nv_bfloat162(h0[0], h0[1]);
            *(__nv_bfloat162*)&PH[(2 * ti) * PP + 4 * tj + 2]     = __nv_bfloat162(h0[2], h0[3]);
            *(__nv_bfloat162*)&PH[(2 * ti + 1) * PP + 4 * tj]     = __nv_bfloat162(h1[0], h1[1]);
            *(__nv_bfloat162*)&PH[(2 * ti + 1) * PP + 4 * tj + 2] = __nv_bfloat162(h1[2], h1[3]);
            *(__nv_bfloat162*)&PL[(2 * ti) * PP + 4 * tj] = __nv_bfloat162(
                __float2bfloat16(p0[0] - __bfloat162float(h0[0])),
                __float2bfloat16(p0[1] - __bfloat162float(h0[1])));
            *(__nv_bfloat162*)&PL[(2 * ti) * PP + 4 * tj + 2] = __nv_bfloat162(
                __float2bfloat16(p0[2] - __bfloat162float(h0[2])),
                __float2bfloat16(p0[3] - __bfloat162float(h0[3])));
            *(__nv_bfloat162*)&PL[(2 * ti + 1) * PP + 4 * tj] = __nv_bfloat162(
                __float2bfloat16(p1[0] - __bfloat162float(h1[0])),
                __float2bfloat16(p1[1] - __bfloat162float(h1[1])));
            *(__nv_bfloat162*)&PL[(2 * ti + 1) * PP + 4 * tj + 2] = __nv_bfloat162(
                __float2bfloat16(p1[2] - __bfloat162float(h1[2])),
                __float2bfloat16(p1[3] - __bfloat162float(h1[3])));
        }
        __syncthreads();   // P + AL visible

        // hoist P fragments (whole 64-key tile) into registers
        unsigned Phf[4][4], Plf[4][4];
#pragma unroll
        for (int ks2 = 0; ks2 < 4; ks2++) {
            unsigned pcol = (ks2 * 16 + psel) * 2;
            ldsm4(Phf[ks2], sb + OPH + prow_a * 144 + pcol);
            ldsm4(Plf[ks2], sb + OPL + prow_a * 144 + pcol);
        }

        // scale accumulators by alpha
        {
            float a0 = AL[rh * 16 + (lane >> 2)];
            float a1 = AL[rh * 16 + (lane >> 2) + 8];
#pragma unroll
            for (int d = 0; d < 8; d++)
#pragma unroll
                for (int nt = 0; nt < 2; nt++) {
                    acc[d][nt][0] *= a0; acc[d][nt][1] *= a0;
                    acc[d][nt][2] *= a1; acc[d][nt][3] *= a1;
                }
        }

        // ---- PV phase over 8 streamed V d-chunks ----
#pragma unroll
        for (int dc = 0; dc < 8; dc++) {
            if (last && dc == 7) cp_wait<0>(); else cp_wait<1>();
            __syncthreads();
            unsigned vb = sb + OCB + (dc & 1) * 18432;
#pragma unroll
            for (int ks2 = 0; ks2 < 4; ks2++) {
                unsigned vrow = (ks2 * 16 + vsrow) * 144;
                unsigned vcol = (vg * 16 + vdoff) * 2;
                unsigned Bh[4], Bl[4];
                ldsm4t(Bh, vb + vrow + vcol);
                ldsm4t(Bl, vb + 9216 + vrow + vcol);
                mma_bf16(acc[dc][0], Phf[ks2], Bh[0], Bh[1]);
                mma_bf16(acc[dc][0], Plf[ks2], Bh[0], Bh[1]);
                mma_bf16(acc[dc][0], Phf[ks2], Bl[0], Bl[1]);
                mma_bf16(acc[dc][1], Phf[ks2], Bh[2], Bh[3]);
                mma_bf16(acc[dc][1], Plf[ks2], Bh[2], Bh[3]);
                mma_bf16(acc[dc][1], Phf[ks2], Bl[2], Bl[3]);
            }
            __syncthreads();
            if (dc < 6)
                attn_load_chunk(sb, dc & 1, g_vh, g_vl, srow0, dc + 2, tid);
            else if (!last)
                attn_load_chunk(sb, dc & 1, g_kh, g_kl, srow0 + 64, dc - 6, tid);
        }
    }

    // ---- epilogue: 1/l, LayerNorm, store ----
    {
        int r  = lane >> 2;
        int c2 = (lane & 3) * 2;
        int row0 = rh * 16 + r;
        int row1 = row0 + 8;
        float linv0 = 1.0f / LL[row0];
        float linv1 = 1.0f / LL[row1];
        float s0 = 0.f, q0 = 0.f, s1 = 0.f, q1 = 0.f;
#pragma unroll
        for (int d = 0; d < 8; d++)
#pragma unroll
            for (int nt = 0; nt < 2; nt++) {
                acc[d][nt][0] *= linv0; acc[d][nt][1] *= linv0;
                acc[d][nt][2] *= linv1; acc[d][nt][3] *= linv1;
                s0 += acc[d][nt][0] + acc[d][nt][1];
                q0 += acc[d][nt][0] * acc[d][nt][0] + acc[d][nt][1] * acc[d][nt][1];
                s1 += acc[d][nt][2] + acc[d][nt][3];
                q1 += acc[d][nt][2] * acc[d][nt][2] + acc[d][nt][3] * acc[d][nt][3];
            }
#pragma unroll
        for (int off = 1; off < 4; off <<= 1) {
            s0 += __shfl_xor_sync(0xffffffffu, s0, off);
            q0 += __shfl_xor_sync(0xffffffffu, q0, off);
            s1 += __shfl_xor_sync(0xffffffffu, s1, off);
            q1 += __shfl_xor_sync(0xffffffffu, q1, off);
        }
        if ((lane & 3) == 0) {
            RS[row0 * 4 + vg] = s0;  RQ[row0 * 4 + vg] = q0;
            RS[row1 * 4 + vg] = s1;  RQ[row1 * 4 + vg] = q1;
        }
        __syncthreads();
        float ts0 = RS[row0 * 4] + RS[row0 * 4 + 1] + RS[row0 * 4 + 2] + RS[row0 * 4 + 3];
        float tq0 = RQ[row0 * 4] + RQ[row0 * 4 + 1] + RQ[row0 * 4 + 2] + RQ[row0 * 4 + 3];
        float ts1 = RS[row1 * 4] + RS[row1 * 4 + 1] + RS[row1 * 4 + 2] + RS[row1 * 4 + 3];
        float tq1 = RQ[row1 * 4] + RQ[row1 * 4 + 1] + RQ[row1 * 4 + 2] + RQ[row1 * 4 + 3];
        const float invD = 1.0f / (float)DIM;
        float mu0 = ts0 * invD, var0 = tq0 * invD - mu0 * mu0;
        float mu1 = ts1 * invD, var1 = tq1 * invD - mu1 * mu1;
        float rstd0 = rsqrtf(var0 + 1e-5f);
        float rstd1 = rsqrtf(var1 + 1e-5f);

        size_t ob0 = (qrow0 + row0) * 512;
        size_t ob1 = (qrow0 + row1) * 512;
#pragma unroll
        for (int d = 0; d < 8; d++)
#pragma unroll
            for (int nt = 0; nt < 2; nt++) {
                int col = d * 64 + vg * 16 + nt * 8 + c2;
                float g0 = gamma[col], g1 = gamma[col + 1];
                float be0 = beta[col], be1 = beta[col + 1];
                float2 o0 = make_float2((acc[d][nt][0] - mu0) * rstd0 * g0 + be0,
                                        (acc[d][nt][1] - mu0) * rstd0 * g1 + be1);
                float2 o1 = make_float2((acc[d][nt][2] - mu1) * rstd1 * g0 + be0,
                                        (acc[d][nt][3] - mu1) * rstd1 * g1 + be1);
                *(float2*)(out + ob0 + col) = o0;
                *(float2*)(out + ob1 + col) = o1;
            }
    }
}

// ---------------------------------------------------------------------------
// Launch
// ---------------------------------------------------------------------------
extern "C" void kernel_launch(void* const* d_in, const int* in_sizes, int n_in,
                              void* d_out, int out_size)
{
    const float* x0    = (const float*)d_in[0];
    const float* x1    = (const float*)d_in[1];
    const float* Wq    = (const float*)d_in[2];
    const float* Wk    = (const float*)d_in[3];
    const float* Wv    = (const float*)d_in[4];
    const float* gamma = (const float*)d_in[5];
    const float* beta  = (const float*)d_in[6];
    float* out = (float*)d_out;

    cudaFuncSetAttribute(qkv_hmma, cudaFuncAttributeMaxDynamicSharedMemorySize, GB_SMEM);
    cudaFuncSetAttribute(attn_mma, cudaFuncAttributeMaxDynamicSharedMemorySize, ATTN_SMEM);

    conv_x<<<MTOT, 256>>>(x0, x1);
    conv_w<<<dim3(16, 32, 3), dim3(32, 8)>>>(Wq, Wk, Wv);
    qkv_hmma<<<dim3(12, 128), 256, GB_SMEM>>>();
    attn_mma<<<dim3(SEQ / 32, BATCH), 256, ATTN_SMEM>>>(gamma, beta, out);
}

// round 12
// speedup vs baseline: 1.3785x; 1.3672x over previous
#include <cuda_runtime.h>
#include <cuda_bf16.h>
#include <cuda_fp16.h>
#include <math.h>

// Problem constants
#define BATCH 8
#define SEQ   2048
#define DIM   512
#define KDIM  1024
#define MTOT  (BATCH*SEQ)   // 16384

// Scratch (no cudaMalloc allowed)
__device__ __nv_bfloat16 g_Ah[(size_t)MTOT * KDIM];
__device__ __nv_bfloat16 g_Al[(size_t)MTOT * KDIM];
__device__ __nv_bfloat16 g_Wh[(size_t)3 * DIM * KDIM];
__device__ __nv_bfloat16 g_Wl[(size_t)3 * DIM * KDIM];
// q/k/v in fp16 (written by GEMM epilogue)
__device__ __half g_qf[(size_t)MTOT * DIM];
__device__ __half g_kf[(size_t)MTOT * DIM];
__device__ __half g_vf[(size_t)MTOT * DIM];

// ---------------------------------------------------------------------------
// helpers
// ---------------------------------------------------------------------------
__device__ __forceinline__ unsigned smem_u32(const void* p) {
    unsigned a;
    asm("{ .reg .u64 t; cvta.to.shared.u64 t, %1; cvt.u32.u64 %0, t; }" : "=r"(a) : "l"(p));
    return a;
}
__device__ __forceinline__ void cpa16(unsigned dst, const void* src) {
    asm volatile("cp.async.cg.shared.global [%0], [%1], 16;"
                 :: "r"(dst), "l"(__cvta_generic_to_global(src)) : "memory");
}
__device__ __forceinline__ void cp_commit() {
    asm volatile("cp.async.commit_group;" ::: "memory");
}
template <int N>
__device__ __forceinline__ void cp_wait() {
    asm volatile("cp.async.wait_group %0;" :: "n"(N) : "memory");
}
__device__ __forceinline__ void ldsm4(unsigned* r, unsigned addr) {
    asm volatile("ldmatrix.sync.aligned.m8n8.x4.shared.b16 {%0,%1,%2,%3}, [%4];"
                 : "=r"(r[0]), "=r"(r[1]), "=r"(r[2]), "=r"(r[3]) : "r"(addr));
}
__device__ __forceinline__ void ldsm4t(unsigned* r, unsigned addr) {
    asm volatile("ldmatrix.sync.aligned.m8n8.x4.trans.shared.b16 {%0,%1,%2,%3}, [%4];"
                 : "=r"(r[0]), "=r"(r[1]), "=r"(r[2]), "=r"(r[3]) : "r"(addr));
}
__device__ __forceinline__ void mma_bf16(float* c, const unsigned* a,
                                         unsigned b0, unsigned b1) {
    asm volatile(
        "mma.sync.aligned.m16n8k16.row.col.f32.bf16.bf16.f32 "
        "{%0,%1,%2,%3}, {%4,%5,%6,%7}, {%8,%9}, {%0,%1,%2,%3};"
        : "+f"(c[0]), "+f"(c[1]), "+f"(c[2]), "+f"(c[3])
        : "r"(a[0]), "r"(a[1]), "r"(a[2]), "r"(a[3]), "r"(b0), "r"(b1));
}
__device__ __forceinline__ void mma_f16(float* c, const unsigned* a,
                                        unsigned b0, unsigned b1) {
    asm volatile(
        "mma.sync.aligned.m16n8k16.row.col.f32.f16.f16.f32 "
        "{%0,%1,%2,%3}, {%4,%5,%6,%7}, {%8,%9}, {%0,%1,%2,%3};"
        : "+f"(c[0]), "+f"(c[1]), "+f"(c[2]), "+f"(c[3])
        : "r"(a[0]), "r"(a[1]), "r"(a[2]), "r"(a[3]), "r"(b0), "r"(b1));
}

// ---------------------------------------------------------------------------
// Conversion: x0|x1 -> bf16 hi/lo, row-major [MTOT][1024]
// ---------------------------------------------------------------------------
__global__ __launch_bounds__(256)
void conv_x(const float* __restrict__ x0, const float* __restrict__ x1)
{
    unsigned t = blockIdx.x * 256u + threadIdx.x;
    unsigned m  = t >> 8;
    unsigned k4 = (t & 255u) * 4u;
    float4 v = (k4 < 512u)
        ? *(const float4*)(x0 + (size_t)m * 512 + k4)
        : *(const float4*)(x1 + (size_t)m * 512 + (k4 - 512u));
    __nv_bfloat16 h0 = __float2bfloat16(v.x);
    __nv_bfloat16 h1 = __float2bfloat16(v.y);
    __nv_bfloat16 h2 = __float2bfloat16(v.z);
    __nv_bfloat16 h3 = __float2bfloat16(v.w);
    __nv_bfloat16 l0 = __float2bfloat16(v.x - __bfloat162float(h0));
    __nv_bfloat16 l1 = __float2bfloat16(v.y - __bfloat162float(h1));
    __nv_bfloat16 l2 = __float2bfloat16(v.z - __bfloat162float(h2));
    __nv_bfloat16 l3 = __float2bfloat16(v.w - __bfloat162float(h3));
    size_t o = (size_t)m * 1024 + k4;
    __nv_bfloat162* dh = (__nv_bfloat162*)(g_Ah + o);
    __nv_bfloat162* dl = (__nv_bfloat162*)(g_Al + o);
    dh[0] = __nv_bfloat162(h0, h1); dh[1] = __nv_bfloat162(h2, h3);
    dl[0] = __nv_bfloat162(l0, l1); dl[1] = __nv_bfloat162(l2, l3);
}

// ---------------------------------------------------------------------------
// W[k][n] -> W^T hi/lo bf16, n-major rows (q scaled by 1/sqrt(D))
// ---------------------------------------------------------------------------
__global__ __launch_bounds__(256)
void conv_w(const float* __restrict__ Wq, const float* __restrict__ Wk,
            const float* __restrict__ Wv)
{
    __shared__ float tile[32][33];
    const int z  = blockIdx.z;
    const float* __restrict__ W = (z == 0) ? Wq : ((z == 1) ? Wk : Wv);
    const int n0 = blockIdx.x * 32;
    const int k0 = blockIdx.y * 32;
    const int tx = threadIdx.x;
    const int ty = threadIdx.y;

    for (int r = ty; r < 32; r += 8)
        tile[r][tx] = W[(size_t)(k0 + r) * 512 + n0 + tx];
    __syncthreads();

    const float scale = (z == 0) ? 0.04419417382415922f : 1.0f;
    for (int r = ty; r < 32; r += 8) {
        int n = n0 + r;
        int k = k0 + tx;
        float v = tile[tx][r] * scale;
        __nv_bfloat16 hi = __float2bfloat16(v);
        __nv_bfloat16 lo = __float2bfloat16(v - __bfloat162float(hi));
        size_t idx = ((size_t)(z * 512 + n)) * 1024 + k;
        g_Wh[idx] = hi;
        g_Wl[idx] = lo;
    }
}

// ---------------------------------------------------------------------------
// QKV GEMM via mma.sync bf16 split-2 (A-fragment pipelined), fp16 epilogue.
// ---------------------------------------------------------------------------
#define GB_BUF 40960
#define GB_SMEM (2 * GB_BUF)

__device__ __forceinline__ void gemm_issue(unsigned sb, int buf, int m0, int nbase,
                                           int k0, int tid)
{
    const int lr  = tid >> 1;
    const int lc0 = (tid & 1) * 2;
    unsigned base = sb + buf * GB_BUF;
    const __nv_bfloat16* pa_h = g_Ah + (size_t)(m0 + lr) * 1024 + k0;
    const __nv_bfloat16* pa_l = g_Al + (size_t)(m0 + lr) * 1024 + k0;
    const __nv_bfloat16* pb_h = g_Wh + (size_t)(nbase + lr) * 1024 + k0;
    const __nv_bfloat16* pb_l = g_Wl + (size_t)(nbase + lr) * 1024 + k0;
#pragma unroll
    for (int cc = 0; cc < 2; cc++) {
        int c = lc0 + cc;
        unsigned o = lr * 80 + c * 16;
        cpa16(base + o,          pa_h + c * 8);
        cpa16(base + 10240 + o,  pa_l + c * 8);
        cpa16(base + 20480 + o,  pb_h + c * 8);
        cpa16(base + 30720 + o,  pb_l + c * 8);
    }
    cp_commit();
}

__global__ __launch_bounds__(256, 2)
void qkv_hmma()
{
    extern __shared__ char smem[];
    unsigned sb = smem_u32(smem);
    const int tid  = threadIdx.x;
    const int lane = tid & 31;
    const int w    = tid >> 5;
    const int wm   = w >> 2;
    const int wn   = w & 3;
    const int nbase = blockIdx.x * 128;
    const int m0    = blockIdx.y * 128;

    float acc[4][4][4];
#pragma unroll
    for (int i = 0; i < 4; i++)
#pragma unroll
        for (int j = 0; j < 4; j++)
#pragma unroll
            for (int k = 0; k < 4; k++) acc[i][j][k] = 0.0f;

    const int mrowA = (lane & 7) + ((lane >> 3) & 1) * 8;
    const int kcA   = (lane >> 4) & 1;
    const int nrowB = (lane & 7) + ((lane >> 4) & 1) * 8;
    const int kcB   = (lane >> 3) & 1;
    const unsigned aoff = (wm * 64 + mrowA) * 80 + kcA * 16;
    const unsigned boff = 20480u + (wn * 32 + nrowB) * 80 + kcB * 16;

    gemm_issue(sb, 0, m0, nbase, 0, tid);

    for (int ch = 0; ch < 32; ++ch) {
        if (ch + 1 < 32) {
            gemm_issue(sb, (ch + 1) & 1, m0, nbase, (ch + 1) * 32, tid);
            cp_wait<1>();
        } else {
            cp_wait<0>();
        }
        __syncthreads();

        unsigned base = sb + (ch & 1) * GB_BUF;
#pragma unroll
        for (int ks = 0; ks < 2; ks++) {
            unsigned Bh[8], Bl[8];
            ldsm4(&Bh[0], base + boff + ks * 32);
            ldsm4(&Bh[4], base + boff + 16 * 80 + ks * 32);
            ldsm4(&Bl[0], base + boff + 10240 + ks * 32);
            ldsm4(&Bl[4], base + boff + 10240 + 16 * 80 + ks * 32);
            unsigned Ahb[2][4], Alb[2][4];
            ldsm4(Ahb[0], base + aoff + ks * 32);
            ldsm4(Alb[0], base + aoff + 10240 + ks * 32);
#pragma unroll
            for (int mt = 0; mt < 4; mt++) {
                int cur = mt & 1;
                if (mt < 3) {
                    ldsm4(Ahb[cur ^ 1], base + aoff + (mt + 1) * (16 * 80) + ks * 32);
                    ldsm4(Alb[cur ^ 1], base + aoff + 10240 + (mt + 1) * (16 * 80) + ks * 32);
                }
#pragma unroll
                for (int nt = 0; nt < 4; nt++) {
                    mma_bf16(acc[mt][nt], Ahb[cur], Bh[nt * 2], Bh[nt * 2 + 1]);
                    mma_bf16(acc[mt][nt], Ahb[cur], Bl[nt * 2], Bl[nt * 2 + 1]);
                    mma_bf16(acc[mt][nt], Alb[cur], Bh[nt * 2], Bh[nt * 2 + 1]);
                }
            }
        }
        __syncthreads();
    }

    // Epilogue: fp32 acc -> fp16 stores
    const int z = nbase >> 9;
    __half* Xf = (z == 0) ? g_qf : ((z == 1) ? g_kf : g_vf);
    const int colb = (nbase & 511) + wn * 32;
    const int gid = lane >> 2, tig = lane & 3;
#pragma unroll
    for (int mt = 0; mt < 4; mt++) {
#pragma unroll
        for (int nt = 0; nt < 4; nt++) {
            int row = m0 + wm * 64 + mt * 16 + gid;
            int col = colb + nt * 8 + tig * 2;
#pragma unroll
            for (int rr = 0; rr < 2; rr++) {
                size_t o = (size_t)(row + rr * 8) * 512 + col;
                *(__half2*)(Xf + o) =
                    __floats2half2_rn(acc[mt][nt][rr * 2 + 0], acc[mt][nt][rr * 2 + 1]);
            }
        }
    }
}

// ---------------------------------------------------------------------------
// fp16 tensor-core flash attention + fused LayerNorm — 2 CTAs/SM.
// CTA = (b, 32-row q-tile), 256 threads (8 warps), smem 78KB.
// KV tiles of 64 keys; K/V streamed as 64-key x 128-d fp16 chunks through
// 2 rotating buffers, 1 chunk lookahead. Single-precision fp16 MMAs.
// ---------------------------------------------------------------------------
#define SD 68        // S pitch fp32
#define PP 72        // P pitch fp16 (144B, odd*16B)

#define OQ  0                    /* 32 x 1040B = 33280 */
#define OCB 33280                /* 2 bufs x 17408 -> 68096 */
#define OSP 68096                /* S 32x68 fp32 (8704), P overlays */
#define OPH 68096                /* fp16 32x72 = 4608 */
#define OAL 76800                /* fp32 32 */
#define OLL 76928                /* fp32 32 */
#define ORS 77056                /* fp32 32x4 */
#define ORQ 77568                /* fp32 32x4 */
#define ATTN_SMEM 78080

#define NEG_INF __int_as_float(0xff800000)

// Load one 64-key x 128-d fp16 chunk of K or V into buffer `buf`.
// 64 rows x 16 x 16B units = 1024 cp.async (4 per thread @256).
__device__ __forceinline__ void attn_load_chunk(unsigned sb, int buf,
                                                const __half* Xf,
                                                size_t srow0, int dc, int tid)
{
#pragma unroll
    for (int i = 0; i < 4; i++) {
        int idx = tid + i * 256;          // 0..1023
        int row = idx >> 4;               // 0..63 (key)
        int c = idx & 15;                 // 16B unit within 128 d (256B)
        const __half* src = Xf + (srow0 + row) * 512 + dc * 128 + c * 8;
        unsigned dst = sb + OCB + buf * 17408 + row * 272 + c * 16;
        cpa16(dst, src);
    }
    cp_commit();
}

__global__ __launch_bounds__(256, 2)
void attn_mma(const float* __restrict__ gamma, const float* __restrict__ beta,
              float* __restrict__ out)
{
    extern __shared__ char smc[];
    unsigned sb = smem_u32(smc);
    float* S    = (float*)(smc + OSP);
    float* AL   = (float*)(smc + OAL);
    float* LL   = (float*)(smc + OLL);
    float* RS   = (float*)(smc + ORS);
    float* RQ   = (float*)(smc + ORQ);
    __half* PH  = (__half*)(smc + OPH);

    const int b   = blockIdx.y;
    const int qb  = gridDim.x - 1 - blockIdx.x;     // heavy tiles first
    const int tid = threadIdx.x;
    const int lane = tid & 31;
    const int w    = tid >> 5;      // 0..7
    const int rh   = w >> 2;        // 0..1 (16-row group)
    const int cg   = w & 3;         // S col group (16 cols)
    const int vg   = w & 3;         // PV col group (32 d-cols per 128-d chunk)
    const int ti = tid >> 4;        // 0..15 -> rows 2ti, 2ti+1
    const int tj = tid & 15;        // cols 4tj..4tj+3

    const size_t qrow0 = (size_t)b * SEQ + (size_t)qb * 32;

    // --- load Q (32 x 512 fp16): 2048 16B units / 256 = 8 per thread ---
#pragma unroll
    for (int i = 0; i < 8; i++) {
        int idx = tid + i * 256;          // 0..2047
        int row = idx >> 6;               // 0..31
        int c = idx & 63;
        const __half* src = g_qf + (qrow0 + row) * 512 + c * 8;
        unsigned dst = sb + OQ + row * 1040 + c * 16;
        cpa16(dst, src);
    }
    cp_commit();

    // PV accumulator: acc[dc][nt][4] — 16 rows x (dc*128 + vg*32 + nt*8) cols
    float acc[4][4][4];
#pragma unroll
    for (int d = 0; d < 4; d++)
#pragma unroll
        for (int nt = 0; nt < 4; nt++)
#pragma unroll
            for (int k = 0; k < 4; k++) acc[d][nt][k] = 0.0f;

    float m0r = NEG_INF, m1r = NEG_INF;
    float l0r = 0.0f,    l1r = 0.0f;

    // ldmatrix lane components
    const unsigned qrow_a = rh * 16 + (lane & 7) + ((lane >> 3) & 1) * 8;
    const unsigned kca    = ((lane >> 4) & 1) * 8;
    const unsigned krow4  = cg * 16 + ((lane >> 4) & 1) * 8 + (lane & 7);
    const unsigned kc4    = ((lane >> 3) & 1) * 8;
    const unsigned prow_a = qrow_a;
    const unsigned psel   = ((lane >> 4) & 1) * 8;
    const unsigned vsrow  = ((lane >> 3) & 1) * 8 + (lane & 7);
    const unsigned vdoff  = ((lane >> 4) & 1) * 8;

    const int jbmax = qb >> 1;   // 64-key tiles; diagonal tile = jbmax

    // prologue: prefetch K d-chunks 0,1 of jb=0
    attn_load_chunk(sb, 0, g_kf, (size_t)b * SEQ, 0, tid);
    attn_load_chunk(sb, 1, g_kf, (size_t)b * SEQ, 1, tid);

    for (int jb = 0; jb <= jbmax; jb++) {
        const size_t srow0 = (size_t)b * SEQ + (size_t)jb * 64;
        const bool last = (jb == jbmax);

        // ---- S phase: S(32x64) = Q Kt over 4 d-chunks of 128 ----
        float s0[4] = {0, 0, 0, 0};
        float s1[4] = {0, 0, 0, 0};
#pragma unroll
        for (int dc = 0; dc < 4; dc++) {
            cp_wait<1>();
            __syncthreads();
            unsigned kb = sb + OCB + (dc & 1) * 17408;
#pragma unroll
            for (int ks = 0; ks < 8; ks++) {
                unsigned qcol = (dc * 128 + ks * 16 + kca) * 2;
                unsigned Qf[4], Kf[4];
                ldsm4(Qf, sb + OQ + qrow_a * 1040 + qcol);
                unsigned kcol = (ks * 16 + kc4) * 2;
                ldsm4(Kf, kb + krow4 * 272 + kcol);
                mma_f16(s0, Qf, Kf[0], Kf[1]);
                mma_f16(s1, Qf, Kf[2], Kf[3]);
            }
            if (dc == 3) {
                int r  = lane >> 2;
                int c2 = (lane & 3) * 2;
                int row0 = rh * 16 + r;
                int col0 = cg * 16 + c2;
                *(float2*)&S[row0 * SD + col0]           = make_float2(s0[0], s0[1]);
                *(float2*)&S[(row0 + 8) * SD + col0]     = make_float2(s0[2], s0[3]);
                *(float2*)&S[row0 * SD + col0 + 8]       = make_float2(s1[0], s1[1]);
                *(float2*)&S[(row0 + 8) * SD + col0 + 8] = make_float2(s1[2], s1[3]);
            }
            __syncthreads();
            if (dc < 2)
                attn_load_chunk(sb, dc & 1, g_kf, srow0, dc + 2, tid);
            else
                attn_load_chunk(sb, dc & 1, g_vf, srow0, dc - 2, tid);
        }

        // ---- softmax (each thread: rows 2ti,2ti+1 x cols 4tj..4tj+3) ----
        {
            float4 v0 = *(float4*)&S[(2 * ti) * SD + 4 * tj];
            float4 v1 = *(float4*)&S[(2 * ti + 1) * SD + 4 * tj];
            float a0[4] = {v0.x, v0.y, v0.z, v0.w};
            float a1[4] = {v1.x, v1.y, v1.z, v1.w};

            if (jb == jbmax) {
                int qi0 = qb * 32 + 2 * ti;
                int kj  = jb * 64 + 4 * tj;
#pragma unroll
                for (int c = 0; c < 4; c++) {
                    if (kj + c > qi0)     a0[c] = NEG_INF;
                    if (kj + c > qi0 + 1) a1[c] = NEG_INF;
                }
            }

            float r0 = fmaxf(fmaxf(a0[0], a0[1]), fmaxf(a0[2], a0[3]));
            float r1 = fmaxf(fmaxf(a1[0], a1[1]), fmaxf(a1[2], a1[3]));
#pragma unroll
            for (int off = 1; off < 16; off <<= 1) {
                r0 = fmaxf(r0, __shfl_xor_sync(0xffffffffu, r0, off));
                r1 = fmaxf(r1, __shfl_xor_sync(0xffffffffu, r1, off));
            }
            float mn0 = fmaxf(m0r, r0);
            float mn1 = fmaxf(m1r, r1);
            float al0 = __expf(m0r - mn0);
            float al1 = __expf(m1r - mn1);

            float p0[4], p1[4];
#pragma unroll
            for (int c = 0; c < 4; c++) {
                p0[c] = __expf(a0[c] - mn0);
                p1[c] = __expf(a1[c] - mn1);
            }
            float rs0 = (p0[0] + p0[1]) + (p0[2] + p0[3]);
            float rs1 = (p1[0] + p1[1]) + (p1[2] + p1[3]);
#pragma unroll
            for (int off = 1; off < 16; off <<= 1) {
                rs0 += __shfl_xor_sync(0xffffffffu, rs0, off);
                rs1 += __shfl_xor_sync(0xffffffffu, rs1, off);
            }
            l0r = al0 * l0r + rs0;  m0r = mn0;
            l1r = al1 * l1r + rs1;  m1r = mn1;

            if (tj == 0) {
                AL[2 * ti]     = al0;
                AL[2 * ti + 1] = al1;
                LL[2 * ti]     = l0r;
                LL[2 * ti + 1] = l1r;
            }
            __syncthreads();   // all S reads done before P overlays S

            *(__half2*)&PH[(2 * ti) * PP + 4 * tj]         = __floats2half2_rn(p0[0], p0[1]);
            *(__half2*)&PH[(2 * ti) * PP + 4 * tj + 2]     = __floats2half2_rn(p0[2], p0[3]);
            *(__half2*)&PH[(2 * ti + 1) * PP + 4 * tj]     = __floats2half2_rn(p1[0], p1[1]);
            *(__half2*)&PH[(2 * ti + 1) * PP + 4 * tj + 2] = __floats2half2_rn(p1[2], p1[3]);
        }
        __syncthreads();   // P + AL visible

        // hoist P fragments (whole 64-key tile) into registers
        unsigned Pf[4][4];
#pragma unroll
        for (int ks2 = 0; ks2 < 4; ks2++) {
            unsigned pcol = (ks2 * 16 + psel) * 2;
            ldsm4(Pf[ks2], sb + OPH + prow_a * 144 + pcol);
        }

        // scale accumulators by alpha
        {
            float a0 = AL[rh * 16 + (lane >> 2)];
            float a1 = AL[rh * 16 + (lane >> 2) + 8];
#pragma unroll
            for (int d = 0; d < 4; d++)
#pragma unroll
                for (int nt = 0; nt < 4; nt++) {
                    acc[d][nt][0] *= a0; acc[d][nt][1] *= a0;
                    acc[d][nt][2] *= a1; acc[d][nt][3] *= a1;
                }
        }

        // ---- PV phase over 4 streamed 128-d V chunks ----
#pragma unroll
        for (int dc = 0; dc < 4; dc++) {
            if (last && dc == 3) cp_wait<0>(); else cp_wait<1>();
            __syncthreads();
            unsigned vb = sb + OCB + (dc & 1) * 17408;
#pragma unroll
            for (int ks2 = 0; ks2 < 4; ks2++) {
                unsigned vrow = (ks2 * 16 + vsrow) * 272;
#pragma unroll
                for (int ng2 = 0; ng2 < 2; ng2++) {
                    unsigned vcol = (vg * 32 + ng2 * 16 + vdoff) * 2;
                    unsigned Vf[4];
                    ldsm4t(Vf, vb + vrow + vcol);
                    mma_f16(acc[dc][ng2 * 2],     Pf[ks2], Vf[0], Vf[1]);
                    mma_f16(acc[dc][ng2 * 2 + 1], Pf[ks2], Vf[2], Vf[3]);
                }
            }
            __syncthreads();
            if (dc < 2)
                attn_load_chunk(sb, dc & 1, g_vf, srow0, dc + 2, tid);
            else if (!last)
                attn_load_chunk(sb, dc & 1, g_kf, srow0 + 64, dc - 2, tid);
        }
    }

    // ---- epilogue: 1/l, LayerNorm, store ----
    {
        int r  = lane >> 2;
        int c2 = (lane & 3) * 2;
        int row0 = rh * 16 + r;
        int row1 = row0 + 8;
        float linv0 = 1.0f / LL[row0];
        float linv1 = 1.0f / LL[row1];
        float s0 = 0.f, q0 = 0.f, s1 = 0.f, q1 = 0.f;
#pragma unroll
        for (int d = 0; d < 4; d++)
#pragma unroll
            for (int nt = 0; nt < 4; nt++) {
                acc[d][nt][0] *= linv0; acc[d][nt][1] *= linv0;
                acc[d][nt][2] *= linv1; acc[d][nt][3] *= linv1;
                s0 += acc[d][nt][0] + acc[d][nt][1];
                q0 += acc[d][nt][0] * acc[d][nt][0] + acc[d][nt][1] * acc[d][nt][1];
                s1 += acc[d][nt][2] + acc[d][nt][3];
                q1 += acc[d][nt][2] * acc[d][nt][2] + acc[d][nt][3] * acc[d][nt][3];
            }
#pragma unroll
        for (int off = 1; off < 4; off <<= 1) {
            s0 += __shfl_xor_sync(0xffffffffu, s0, off);
            q0 += __shfl_xor_sync(0xffffffffu, q0, off);
            s1 += __shfl_xor_sync(0xffffffffu, s1, off);
            q1 += __shfl_xor_sync(0xffffffffu, q1, off);
        }
        if ((lane & 3) == 0) {
            RS[row0 * 4 + vg] = s0;  RQ[row0 * 4 + vg] = q0;
            RS[row1 * 4 + vg] = s1;  RQ[row1 * 4 + vg] = q1;
        }
        __syncthreads();
        float ts0 = RS[row0 * 4] + RS[row0 * 4 + 1] + RS[row0 * 4 + 2] + RS[row0 * 4 + 3];
        float tq0 = RQ[row0 * 4] + RQ[row0 * 4 + 1] + RQ[row0 * 4 + 2] + RQ[row0 * 4 + 3];
        float ts1 = RS[row1 * 4] + RS[row1 * 4 + 1] + RS[row1 * 4 + 2] + RS[row1 * 4 + 3];
        float tq1 = RQ[row1 * 4] + RQ[row1 * 4 + 1] + RQ[row1 * 4 + 2] + RQ[row1 * 4 + 3];
        const float invD = 1.0f / (float)DIM;
        float mu0 = ts0 * invD, var0 = tq0 * invD - mu0 * mu0;
        float mu1 = ts1 * invD, var1 = tq1 * invD - mu1 * mu1;
        float rstd0 = rsqrtf(var0 + 1e-5f);
        float rstd1 = rsqrtf(var1 + 1e-5f);

        size_t ob0 = (qrow0 + row0) * 512;
        size_t ob1 = (qrow0 + row1) * 512;
#pragma unroll
        for (int d = 0; d < 4; d++)
#pragma unroll
            for (int nt = 0; nt < 4; nt++) {
                int col = d * 128 + vg * 32 + nt * 8 + c2;
                float g0 = gamma[col], g1 = gamma[col + 1];
                float be0 = beta[col], be1 = beta[col + 1];
                float2 o0 = make_float2((acc[d][nt][0] - mu0) * rstd0 * g0 + be0,
                                        (acc[d][nt][1] - mu0) * rstd0 * g1 + be1);
                float2 o1 = make_float2((acc[d][nt][2] - mu1) * rstd1 * g0 + be0,
                                        (acc[d][nt][3] - mu1) * rstd1 * g1 + be1);
                *(float2*)(out + ob0 + col) = o0;
                *(float2*)(out + ob1 + col) = o1;
            }
    }
}

// ---------------------------------------------------------------------------
// Launch
// ---------------------------------------------------------------------------
extern "C" void kernel_launch(void* const* d_in, const int* in_sizes, int n_in,
                              void* d_out, int out_size)
{
    const float* x0    = (const float*)d_in[0];
    const float* x1    = (const float*)d_in[1];
    const float* Wq    = (const float*)d_in[2];
    const float* Wk    = (const float*)d_in[3];
    const float* Wv    = (const float*)d_in[4];
    const float* gamma = (const float*)d_in[5];
    const float* beta  = (const float*)d_in[6];
    float* out = (float*)d_out;

    cudaFuncSetAttribute(qkv_hmma, cudaFuncAttributeMaxDynamicSharedMemorySize, GB_SMEM);
    cudaFuncSetAttribute(attn_mma, cudaFuncAttributeMaxDynamicSharedMemorySize, ATTN_SMEM);

    conv_x<<<MTOT, 256>>>(x0, x1);
    conv_w<<<dim3(16, 32, 3), dim3(32, 8)>>>(Wq, Wk, Wv);
    qkv_hmma<<<dim3(12, 128), 256, GB_SMEM>>>();
    attn_mma<<<dim3(SEQ / 32, BATCH), 256, ATTN_SMEM>>>(gamma, beta, out);
}

// round 13
// speedup vs baseline: 2.2184x; 1.6093x over previous
#include <cuda_runtime.h>
#include <cuda_bf16.h>
#include <cuda_fp16.h>
#include <math.h>

// Problem constants
#define BATCH 8
#define SEQ   2048
#define DIM   512
#define KDIM  1024
#define MTOT  (BATCH*SEQ)   // 16384

// Scratch (no cudaMalloc allowed)
__device__ __half g_xf[(size_t)MTOT * KDIM];        // x concat, fp16
__device__ __half g_wf[(size_t)3 * DIM * KDIM];     // W^T rows [q|k|v], fp16
__device__ __half g_qf[(size_t)MTOT * DIM];
__device__ __half g_kf[(size_t)MTOT * DIM];
__device__ __half g_vf[(size_t)MTOT * DIM];

// ---------------------------------------------------------------------------
// helpers
// ---------------------------------------------------------------------------
__device__ __forceinline__ unsigned smem_u32(const void* p) {
    unsigned a;
    asm("{ .reg .u64 t; cvta.to.shared.u64 t, %1; cvt.u32.u64 %0, t; }" : "=r"(a) : "l"(p));
    return a;
}
__device__ __forceinline__ void cpa16(unsigned dst, const void* src) {
    asm volatile("cp.async.cg.shared.global [%0], [%1], 16;"
                 :: "r"(dst), "l"(__cvta_generic_to_global(src)) : "memory");
}
__device__ __forceinline__ void cp_commit() {
    asm volatile("cp.async.commit_group;" ::: "memory");
}
template <int N>
__device__ __forceinline__ void cp_wait() {
    asm volatile("cp.async.wait_group %0;" :: "n"(N) : "memory");
}
__device__ __forceinline__ void ldsm4(unsigned* r, unsigned addr) {
    asm volatile("ldmatrix.sync.aligned.m8n8.x4.shared.b16 {%0,%1,%2,%3}, [%4];"
                 : "=r"(r[0]), "=r"(r[1]), "=r"(r[2]), "=r"(r[3]) : "r"(addr));
}
__device__ __forceinline__ void ldsm4t(unsigned* r, unsigned addr) {
    asm volatile("ldmatrix.sync.aligned.m8n8.x4.trans.shared.b16 {%0,%1,%2,%3}, [%4];"
                 : "=r"(r[0]), "=r"(r[1]), "=r"(r[2]), "=r"(r[3]) : "r"(addr));
}
__device__ __forceinline__ void mma_f16(float* c, const unsigned* a,
                                        unsigned b0, unsigned b1) {
    asm volatile(
        "mma.sync.aligned.m16n8k16.row.col.f32.f16.f16.f32 "
        "{%0,%1,%2,%3}, {%4,%5,%6,%7}, {%8,%9}, {%0,%1,%2,%3};"
        : "+f"(c[0]), "+f"(c[1]), "+f"(c[2]), "+f"(c[3])
        : "r"(a[0]), "r"(a[1]), "r"(a[2]), "r"(a[3]), "r"(b0), "r"(b1));
}

// ---------------------------------------------------------------------------
// Conversion: x0|x1 -> fp16, row-major [MTOT][1024]
// ---------------------------------------------------------------------------
__global__ __launch_bounds__(256)
void conv_x(const float* __restrict__ x0, const float* __restrict__ x1)
{
    unsigned t = blockIdx.x * 256u + threadIdx.x;
    unsigned m  = t >> 8;
    unsigned k4 = (t & 255u) * 4u;
    float4 v = (k4 < 512u)
        ? *(const float4*)(x0 + (size_t)m * 512 + k4)
        : *(const float4*)(x1 + (size_t)m * 512 + (k4 - 512u));
    __half2* d = (__half2*)(g_xf + (size_t)m * 1024 + k4);
    d[0] = __floats2half2_rn(v.x, v.y);
    d[1] = __floats2half2_rn(v.z, v.w);
}

// ---------------------------------------------------------------------------
// W[k][n] -> W^T fp16, n-major rows (q scaled by 1/sqrt(D))
// ---------------------------------------------------------------------------
__global__ __launch_bounds__(256)
void conv_w(const float* __restrict__ Wq, const float* __restrict__ Wk,
            const float* __restrict__ Wv)
{
    __shared__ float tile[32][33];
    const int z  = blockIdx.z;
    const float* __restrict__ W = (z == 0) ? Wq : ((z == 1) ? Wk : Wv);
    const int n0 = blockIdx.x * 32;
    const int k0 = blockIdx.y * 32;
    const int tx = threadIdx.x;
    const int ty = threadIdx.y;

    for (int r = ty; r < 32; r += 8)
        tile[r][tx] = W[(size_t)(k0 + r) * 512 + n0 + tx];
    __syncthreads();

    const float scale = (z == 0) ? 0.04419417382415922f : 1.0f;
    for (int r = ty; r < 32; r += 8) {
        int n = n0 + r;
        int k = k0 + tx;
        g_wf[((size_t)(z * 512 + n)) * 1024 + k] = __float2half_rn(tile[tx][r] * scale);
    }
}

// ---------------------------------------------------------------------------
// QKV GEMM via mma.sync fp16 (single precision), A-fragment pipelined.
// CTA tile M=128 x N=128, BK=32, 8 warps (2x4), double-buffered cp.async.
// smem rows pitch 80B. grid = (12, 128).
// ---------------------------------------------------------------------------
#define GF_BUF 20480
#define GF_SMEM (2 * GF_BUF)

__device__ __forceinline__ void gemm_issue(unsigned sb, int buf, int m0, int nbase,
                                           int k0, int tid)
{
    unsigned base = sb + buf * GF_BUF;
#pragma unroll
    for (int i = 0; i < 4; i++) {
        int idx = tid + i * 256;          // 0..1023
        int which = idx >> 9;             // 0:A 1:B
        int u = idx & 511;
        int row = u >> 2;                 // 0..127
        int c = u & 3;                    // 16B unit within 32 k (64B)
        const __half* src = which
            ? (g_wf + (size_t)(nbase + row) * 1024 + k0 + c * 8)
            : (g_xf + (size_t)(m0 + row) * 1024 + k0 + c * 8);
        cpa16(base + which * 10240 + row * 80 + c * 16, src);
    }
    cp_commit();
}

__global__ __launch_bounds__(256, 2)
void qkv_hmma()
{
    extern __shared__ char smem[];
    unsigned sb = smem_u32(smem);
    const int tid  = threadIdx.x;
    const int lane = tid & 31;
    const int w    = tid >> 5;
    const int wm   = w >> 2;
    const int wn   = w & 3;
    const int nbase = blockIdx.x * 128;
    const int m0    = blockIdx.y * 128;

    float acc[4][4][4];
#pragma unroll
    for (int i = 0; i < 4; i++)
#pragma unroll
        for (int j = 0; j < 4; j++)
#pragma unroll
            for (int k = 0; k < 4; k++) acc[i][j][k] = 0.0f;

    const int mrowA = (lane & 7) + ((lane >> 3) & 1) * 8;
    const int kcA   = (lane >> 4) & 1;
    const int nrowB = (lane & 7) + ((lane >> 4) & 1) * 8;
    const int kcB   = (lane >> 3) & 1;
    const unsigned aoff = (wm * 64 + mrowA) * 80 + kcA * 16;
    const unsigned boff = 10240u + (wn * 32 + nrowB) * 80 + kcB * 16;

    gemm_issue(sb, 0, m0, nbase, 0, tid);

    for (int ch = 0; ch < 32; ++ch) {
        if (ch + 1 < 32) {
            gemm_issue(sb, (ch + 1) & 1, m0, nbase, (ch + 1) * 32, tid);
            cp_wait<1>();
        } else {
            cp_wait<0>();
        }
        __syncthreads();

        unsigned base = sb + (ch & 1) * GF_BUF;
#pragma unroll
        for (int ks = 0; ks < 2; ks++) {
            unsigned B8[8];
            ldsm4(&B8[0], base + boff + ks * 32);
            ldsm4(&B8[4], base + boff + 16 * 80 + ks * 32);
            unsigned Ab[2][4];
            ldsm4(Ab[0], base + aoff + ks * 32);
#pragma unroll
            for (int mt = 0; mt < 4; mt++) {
                int cur = mt & 1;
                if (mt < 3)
                    ldsm4(Ab[cur ^ 1], base + aoff + (mt + 1) * (16 * 80) + ks * 32);
#pragma unroll
                for (int nt = 0; nt < 4; nt++)
                    mma_f16(acc[mt][nt], Ab[cur], B8[nt * 2], B8[nt * 2 + 1]);
            }
        }
        __syncthreads();
    }

    // Epilogue: fp32 acc -> fp16 stores
    const int z = nbase >> 9;
    __half* Xf = (z == 0) ? g_qf : ((z == 1) ? g_kf : g_vf);
    const int colb = (nbase & 511) + wn * 32;
    const int gid = lane >> 2, tig = lane & 3;
#pragma unroll
    for (int mt = 0; mt < 4; mt++) {
#pragma unroll
        for (int nt = 0; nt < 4; nt++) {
            int row = m0 + wm * 64 + mt * 16 + gid;
            int col = colb + nt * 8 + tig * 2;
#pragma unroll
            for (int rr = 0; rr < 2; rr++) {
                size_t o = (size_t)(row + rr * 8) * 512 + col;
                *(__half2*)(Xf + o) =
                    __floats2half2_rn(acc[mt][nt][rr * 2 + 0], acc[mt][nt][rr * 2 + 1]);
            }
        }
    }
}

// ---------------------------------------------------------------------------
// fp16 tensor-core flash attention + fused LayerNorm — 2 CTAs/SM.
// (byte-identical to R12's passing version)
// ---------------------------------------------------------------------------
#define SD 68        // S pitch fp32
#define PP 72        // P pitch fp16 (144B, odd*16B)

#define OQ  0                    /* 32 x 1040B = 33280 */
#define OCB 33280                /* 2 bufs x 17408 -> 68096 */
#define OSP 68096                /* S 32x68 fp32 (8704), P overlays */
#define OPH 68096                /* fp16 32x72 = 4608 */
#define OAL 76800                /* fp32 32 */
#define OLL 76928                /* fp32 32 */
#define ORS 77056                /* fp32 32x4 */
#define ORQ 77568                /* fp32 32x4 */
#define ATTN_SMEM 78080

#define NEG_INF __int_as_float(0xff800000)

__device__ __forceinline__ void attn_load_chunk(unsigned sb, int buf,
                                                const __half* Xf,
                                                size_t srow0, int dc, int tid)
{
#pragma unroll
    for (int i = 0; i < 4; i++) {
        int idx = tid + i * 256;          // 0..1023
        int row = idx >> 4;               // 0..63 (key)
        int c = idx & 15;                 // 16B unit within 128 d (256B)
        const __half* src = Xf + (srow0 + row) * 512 + dc * 128 + c * 8;
        unsigned dst = sb + OCB + buf * 17408 + row * 272 + c * 16;
        cpa16(dst, src);
    }
    cp_commit();
}

__global__ __launch_bounds__(256, 2)
void attn_mma(const float* __restrict__ gamma, const float* __restrict__ beta,
              float* __restrict__ out)
{
    extern __shared__ char smc[];
    unsigned sb = smem_u32(smc);
    float* S    = (float*)(smc + OSP);
    float* AL   = (float*)(smc + OAL);
    float* LL   = (float*)(smc + OLL);
    float* RS   = (float*)(smc + ORS);
    float* RQ   = (float*)(smc + ORQ);
    __half* PH  = (__half*)(smc + OPH);

    const int b   = blockIdx.y;
    const int qb  = gridDim.x - 1 - blockIdx.x;     // heavy tiles first
    const int tid = threadIdx.x;
    const int lane = tid & 31;
    const int w    = tid >> 5;      // 0..7
    const int rh   = w >> 2;        // 0..1 (16-row group)
    const int cg   = w & 3;         // S col group (16 cols)
    const int vg   = w & 3;         // PV col group (32 d-cols per 128-d chunk)
    const int ti = tid >> 4;        // 0..15 -> rows 2ti, 2ti+1
    const int tj = tid & 15;        // cols 4tj..4tj+3

    const size_t qrow0 = (size_t)b * SEQ + (size_t)qb * 32;

    // --- load Q (32 x 512 fp16): 8 units per thread ---
#pragma unroll
    for (int i = 0; i < 8; i++) {
        int idx = tid + i * 256;          // 0..2047
        int row = idx >> 6;               // 0..31
        int c = idx & 63;
        const __half* src = g_qf + (qrow0 + row) * 512 + c * 8;
        unsigned dst = sb + OQ + row * 1040 + c * 16;
        cpa16(dst, src);
    }
    cp_commit();

    float acc[4][4][4];
#pragma unroll
    for (int d = 0; d < 4; d++)
#pragma unroll
        for (int nt = 0; nt < 4; nt++)
#pragma unroll
            for (int k = 0; k < 4; k++) acc[d][nt][k] = 0.0f;

    float m0r = NEG_INF, m1r = NEG_INF;
    float l0r = 0.0f,    l1r = 0.0f;

    const unsigned qrow_a = rh * 16 + (lane & 7) + ((lane >> 3) & 1) * 8;
    const unsigned kca    = ((lane >> 4) & 1) * 8;
    const unsigned krow4  = cg * 16 + ((lane >> 4) & 1) * 8 + (lane & 7);
    const unsigned kc4    = ((lane >> 3) & 1) * 8;
    const unsigned prow_a = qrow_a;
    const unsigned psel   = ((lane >> 4) & 1) * 8;
    const unsigned vsrow  = ((lane >> 3) & 1) * 8 + (lane & 7);
    const unsigned vdoff  = ((lane >> 4) & 1) * 8;

    const int jbmax = qb >> 1;   // 64-key tiles; diagonal tile = jbmax

    attn_load_chunk(sb, 0, g_kf, (size_t)b * SEQ, 0, tid);
    attn_load_chunk(sb, 1, g_kf, (size_t)b * SEQ, 1, tid);

    for (int jb = 0; jb <= jbmax; jb++) {
        const size_t srow0 = (size_t)b * SEQ + (size_t)jb * 64;
        const bool last = (jb == jbmax);

        // ---- S phase: S(32x64) = Q Kt over 4 d-chunks of 128 ----
        float s0[4] = {0, 0, 0, 0};
        float s1[4] = {0, 0, 0, 0};
#pragma unroll
        for (int dc = 0; dc < 4; dc++) {
            cp_wait<1>();
            __syncthreads();
            unsigned kb = sb + OCB + (dc & 1) * 17408;
#pragma unroll
            for (int ks = 0; ks < 8; ks++) {
                unsigned qcol = (dc * 128 + ks * 16 + kca) * 2;
                unsigned Qf[4], Kf[4];
                ldsm4(Qf, sb + OQ + qrow_a * 1040 + qcol);
                unsigned kcol = (ks * 16 + kc4) * 2;
                ldsm4(Kf, kb + krow4 * 272 + kcol);
                mma_f16(s0, Qf, Kf[0], Kf[1]);
                mma_f16(s1, Qf, Kf[2], Kf[3]);
            }
            if (dc == 3) {
                int r  = lane >> 2;
                int c2 = (lane & 3) * 2;
                int row0 = rh * 16 + r;
                int col0 = cg * 16 + c2;
                *(float2*)&S[row0 * SD + col0]           = make_float2(s0[0], s0[1]);
                *(float2*)&S[(row0 + 8) * SD + col0]     = make_float2(s0[2], s0[3]);
                *(float2*)&S[row0 * SD + col0 + 8]       = make_float2(s1[0], s1[1]);
                *(float2*)&S[(row0 + 8) * SD + col0 + 8] = make_float2(s1[2], s1[3]);
            }
            __syncthreads();
            if (dc < 2)
                attn_load_chunk(sb, dc & 1, g_kf, srow0, dc + 2, tid);
            else
                attn_load_chunk(sb, dc & 1, g_vf, srow0, dc - 2, tid);
        }

        // ---- softmax ----
        {
            float4 v0 = *(float4*)&S[(2 * ti) * SD + 4 * tj];
            float4 v1 = *(float4*)&S[(2 * ti + 1) * SD + 4 * tj];
            float a0[4] = {v0.x, v0.y, v0.z, v0.w};
            float a1[4] = {v1.x, v1.y, v1.z, v1.w};

            if (jb == jbmax) {
                int qi0 = qb * 32 + 2 * ti;
                int kj  = jb * 64 + 4 * tj;
#pragma unroll
                for (int c = 0; c < 4; c++) {
                    if (kj + c > qi0)     a0[c] = NEG_INF;
                    if (kj + c > qi0 + 1) a1[c] = NEG_INF;
                }
            }

            float r0 = fmaxf(fmaxf(a0[0], a0[1]), fmaxf(a0[2], a0[3]));
            float r1 = fmaxf(fmaxf(a1[0], a1[1]), fmaxf(a1[2], a1[3]));
#pragma unroll
            for (int off = 1; off < 16; off <<= 1) {
                r0 = fmaxf(r0, __shfl_xor_sync(0xffffffffu, r0, off));
                r1 = fmaxf(r1, __shfl_xor_sync(0xffffffffu, r1, off));
            }
            float mn0 = fmaxf(m0r, r0);
            float mn1 = fmaxf(m1r, r1);
            float al0 = __expf(m0r - mn0);
            float al1 = __expf(m1r - mn1);

            float p0[4], p1[4];
#pragma unroll
            for (int c = 0; c < 4; c++) {
                p0[c] = __expf(a0[c] - mn0);
                p1[c] = __expf(a1[c] - mn1);
            }
            float rs0 = (p0[0] + p0[1]) + (p0[2] + p0[3]);
            float rs1 = (p1[0] + p1[1]) + (p1[2] + p1[3]);
#pragma unroll
            for (int off = 1; off < 16; off <<= 1) {
                rs0 += __shfl_xor_sync(0xffffffffu, rs0, off);
                rs1 += __shfl_xor_sync(0xffffffffu, rs1, off);
            }
            l0r = al0 * l0r + rs0;  m0r = mn0;
            l1r = al1 * l1r + rs1;  m1r = mn1;

            if (tj == 0) {
                AL[2 * ti]     = al0;
                AL[2 * ti + 1] = al1;
                LL[2 * ti]     = l0r;
                LL[2 * ti + 1] = l1r;
            }
            __syncthreads();   // all S reads done before P overlays S

            *(__half2*)&PH[(2 * ti) * PP + 4 * tj]         = __floats2half2_rn(p0[0], p0[1]);
            *(__half2*)&PH[(2 * ti) * PP + 4 * tj + 2]     = __floats2half2_rn(p0[2], p0[3]);
            *(__half2*)&PH[(2 * ti + 1) * PP + 4 * tj]     = __floats2half2_rn(p1[0], p1[1]);
            *(__half2*)&PH[(2 * ti + 1) * PP + 4 * tj + 2] = __floats2half2_rn(p1[2], p1[3]);
        }
        __syncthreads();   // P + AL visible

        unsigned Pf[4][4];
#pragma unroll
        for (int ks2 = 0; ks2 < 4; ks2++) {
            unsigned pcol = (ks2 * 16 + psel) * 2;
            ldsm4(Pf[ks2], sb + OPH + prow_a * 144 + pcol);
        }

        {
            float a0 = AL[rh * 16 + (lane >> 2)];
            float a1 = AL[rh * 16 + (lane >> 2) + 8];
#pragma unroll
            for (int d = 0; d < 4; d++)
#pragma unroll
                for (int nt = 0; nt < 4; nt++) {
                    acc[d][nt][0] *= a0; acc[d][nt][1] *= a0;
                    acc[d][nt][2] *= a1; acc[d][nt][3] *= a1;
                }
        }

        // ---- PV phase over 4 streamed 128-d V chunks ----
#pragma unroll
        for (int dc = 0; dc < 4; dc++) {
            if (last && dc == 3) cp_wait<0>(); else cp_wait<1>();
            __syncthreads();
            unsigned vb = sb + OCB + (dc & 1) * 17408;
#pragma unroll
            for (int ks2 = 0; ks2 < 4; ks2++) {
                unsigned vrow = (ks2 * 16 + vsrow) * 272;
#pragma unroll
                for (int ng2 = 0; ng2 < 2; ng2++) {
                    unsigned vcol = (vg * 32 + ng2 * 16 + vdoff) * 2;
                    unsigned Vf[4];
                    ldsm4t(Vf, vb + vrow + vcol);
                    mma_f16(acc[dc][ng2 * 2],     Pf[ks2], Vf[0], Vf[1]);
                    mma_f16(acc[dc][ng2 * 2 + 1], Pf[ks2], Vf[2], Vf[3]);
                }
            }
            __syncthreads();
            if (dc < 2)
                attn_load_chunk(sb, dc & 1, g_vf, srow0, dc + 2, tid);
            else if (!last)
                attn_load_chunk(sb, dc & 1, g_kf, srow0 + 64, dc - 2, tid);
        }
    }

    // ---- epilogue: 1/l, LayerNorm, store ----
    {
        int r  = lane >> 2;
        int c2 = (lane & 3) * 2;
        int row0 = rh * 16 + r;
        int row1 = row0 + 8;
        float linv0 = 1.0f / LL[row0];
        float linv1 = 1.0f / LL[row1];
        float s0 = 0.f, q0 = 0.f, s1 = 0.f, q1 = 0.f;
#pragma unroll
        for (int d = 0; d < 4; d++)
#pragma unroll
            for (int nt = 0; nt < 4; nt++) {
                acc[d][nt][0] *= linv0; acc[d][nt][1] *= linv0;
                acc[d][nt][2] *= linv1; acc[d][nt][3] *= linv1;
                s0 += acc[d][nt][0] + acc[d][nt][1];
                q0 += acc[d][nt][0] * acc[d][nt][0] + acc[d][nt][1] * acc[d][nt][1];
                s1 += acc[d][nt][2] + acc[d][nt][3];
                q1 += acc[d][nt][2] * acc[d][nt][2] + acc[d][nt][3] * acc[d][nt][3];
            }
#pragma unroll
        for (int off = 1; off < 4; off <<= 1) {
            s0 += __shfl_xor_sync(0xffffffffu, s0, off);
            q0 += __shfl_xor_sync(0xffffffffu, q0, off);
            s1 += __shfl_xor_sync(0xffffffffu, s1, off);
            q1 += __shfl_xor_sync(0xffffffffu, q1, off);
        }
        if ((lane & 3) == 0) {
            RS[row0 * 4 + vg] = s0;  RQ[row0 * 4 + vg] = q0;
            RS[row1 * 4 + vg] = s1;  RQ[row1 * 4 + vg] = q1;
        }
        __syncthreads();
        float ts0 = RS[row0 * 4] + RS[row0 * 4 + 1] + RS[row0 * 4 + 2] + RS[row0 * 4 + 3];
        float tq0 = RQ[row0 * 4] + RQ[row0 * 4 + 1] + RQ[row0 * 4 + 2] + RQ[row0 * 4 + 3];
        float ts1 = RS[row1 * 4] + RS[row1 * 4 + 1] + RS[row1 * 4 + 2] + RS[row1 * 4 + 3];
        float tq1 = RQ[row1 * 4] + RQ[row1 * 4 + 1] + RQ[row1 * 4 + 2] + RQ[row1 * 4 + 3];
        const float invD = 1.0f / (float)DIM;
        float mu0 = ts0 * invD, var0 = tq0 * invD - mu0 * mu0;
        float mu1 = ts1 * invD, var1 = tq1 * invD - mu1 * mu1;
        float rstd0 = rsqrtf(var0 + 1e-5f);
        float rstd1 = rsqrtf(var1 + 1e-5f);

        size_t ob0 = (qrow0 + row0) * 512;
        size_t ob1 = (qrow0 + row1) * 512;
#pragma unroll
        for (int d = 0; d < 4; d++)
#pragma unroll
            for (int nt = 0; nt < 4; nt++) {
                int col = d * 128 + vg * 32 + nt * 8 + c2;
                float g0 = gamma[col], g1 = gamma[col + 1];
                float be0 = beta[col], be1 = beta[col + 1];
                float2 o0 = make_float2((acc[d][nt][0] - mu0) * rstd0 * g0 + be0,
                                        (acc[d][nt][1] - mu0) * rstd0 * g1 + be1);
                float2 o1 = make_float2((acc[d][nt][2] - mu1) * rstd1 * g0 + be0,
                                        (acc[d][nt][3] - mu1) * rstd1 * g1 + be1);
                *(float2*)(out + ob0 + col) = o0;
                *(float2*)(out + ob1 + col) = o1;
            }
    }
}

// ---------------------------------------------------------------------------
// Launch
// ---------------------------------------------------------------------------
extern "C" void kernel_launch(void* const* d_in, const int* in_sizes, int n_in,
                              void* d_out, int out_size)
{
    const float* x0    = (const float*)d_in[0];
    const float* x1    = (const float*)d_in[1];
    const float* Wq    = (const float*)d_in[2];
    const float* Wk    = (const float*)d_in[3];
    const float* Wv    = (const float*)d_in[4];
    const float* gamma = (const float*)d_in[5];
    const float* beta  = (const float*)d_in[6];
    float* out = (float*)d_out;

    cudaFuncSetAttribute(qkv_hmma, cudaFuncAttributeMaxDynamicSharedMemorySize, GF_SMEM);
    cudaFuncSetAttribute(attn_mma, cudaFuncAttributeMaxDynamicSharedMemorySize, ATTN_SMEM);

    conv_x<<<MTOT, 256>>>(x0, x1);
    conv_w<<<dim3(16, 32, 3), dim3(32, 8)>>>(Wq, Wk, Wv);
    qkv_hmma<<<dim3(12, 128), 256, GF_SMEM>>>();
    attn_mma<<<dim3(SEQ / 32, BATCH), 256, ATTN_SMEM>>>(gamma, beta, out);
}

// round 14
// speedup vs baseline: 2.2852x; 1.0301x over previous
#include <cuda_runtime.h>
#include <cuda_bf16.h>
#include <cuda_fp16.h>
#include <math.h>

// Problem constants
#define BATCH 8
#define SEQ   2048
#define DIM   512
#define KDIM  1024
#define MTOT  (BATCH*SEQ)   // 16384

// Scratch (no cudaMalloc allowed)
__device__ __half g_xf[(size_t)MTOT * KDIM];        // x concat, fp16
__device__ __half g_wf[(size_t)3 * DIM * KDIM];     // W^T rows [q|k|v], fp16
__device__ __half g_qf[(size_t)MTOT * DIM];
__device__ __half g_kf[(size_t)MTOT * DIM];
__device__ __half g_vf[(size_t)MTOT * DIM];

// ---------------------------------------------------------------------------
// helpers
// ---------------------------------------------------------------------------
__device__ __forceinline__ unsigned smem_u32(const void* p) {
    unsigned a;
    asm("{ .reg .u64 t; cvta.to.shared.u64 t, %1; cvt.u32.u64 %0, t; }" : "=r"(a) : "l"(p));
    return a;
}
__device__ __forceinline__ void cpa16(unsigned dst, const void* src) {
    asm volatile("cp.async.cg.shared.global [%0], [%1], 16;"
                 :: "r"(dst), "l"(__cvta_generic_to_global(src)) : "memory");
}
__device__ __forceinline__ void cp_commit() {
    asm volatile("cp.async.commit_group;" ::: "memory");
}
template <int N>
__device__ __forceinline__ void cp_wait() {
    asm volatile("cp.async.wait_group %0;" :: "n"(N) : "memory");
}
__device__ __forceinline__ void ldsm4(unsigned* r, unsigned addr) {
    asm volatile("ldmatrix.sync.aligned.m8n8.x4.shared.b16 {%0,%1,%2,%3}, [%4];"
                 : "=r"(r[0]), "=r"(r[1]), "=r"(r[2]), "=r"(r[3]) : "r"(addr));
}
__device__ __forceinline__ void ldsm4t(unsigned* r, unsigned addr) {
    asm volatile("ldmatrix.sync.aligned.m8n8.x4.trans.shared.b16 {%0,%1,%2,%3}, [%4];"
                 : "=r"(r[0]), "=r"(r[1]), "=r"(r[2]), "=r"(r[3]) : "r"(addr));
}
__device__ __forceinline__ void mma_f16(float* c, const unsigned* a,
                                        unsigned b0, unsigned b1) {
    asm volatile(
        "mma.sync.aligned.m16n8k16.row.col.f32.f16.f16.f32 "
        "{%0,%1,%2,%3}, {%4,%5,%6,%7}, {%8,%9}, {%0,%1,%2,%3};"
        : "+f"(c[0]), "+f"(c[1]), "+f"(c[2]), "+f"(c[3])
        : "r"(a[0]), "r"(a[1]), "r"(a[2]), "r"(a[3]), "r"(b0), "r"(b1));
}

// ---------------------------------------------------------------------------
// Conversion: x0|x1 -> fp16, row-major [MTOT][1024]
// ---------------------------------------------------------------------------
__global__ __launch_bounds__(256)
void conv_x(const float* __restrict__ x0, const float* __restrict__ x1)
{
    unsigned t = blockIdx.x * 256u + threadIdx.x;
    unsigned m  = t >> 8;
    unsigned k4 = (t & 255u) * 4u;
    float4 v = (k4 < 512u)
        ? *(const float4*)(x0 + (size_t)m * 512 + k4)
        : *(const float4*)(x1 + (size_t)m * 512 + (k4 - 512u));
    __half2* d = (__half2*)(g_xf + (size_t)m * 1024 + k4);
    d[0] = __floats2half2_rn(v.x, v.y);
    d[1] = __floats2half2_rn(v.z, v.w);
}

// ---------------------------------------------------------------------------
// W[k][n] -> W^T fp16, n-major rows (q scaled by 1/sqrt(D))
// ---------------------------------------------------------------------------
__global__ __launch_bounds__(256)
void conv_w(const float* __restrict__ Wq, const float* __restrict__ Wk,
            const float* __restrict__ Wv)
{
    __shared__ float tile[32][33];
    const int z  = blockIdx.z;
    const float* __restrict__ W = (z == 0) ? Wq : ((z == 1) ? Wk : Wv);
    const int n0 = blockIdx.x * 32;
    const int k0 = blockIdx.y * 32;
    const int tx = threadIdx.x;
    const int ty = threadIdx.y;

    for (int r = ty; r < 32; r += 8)
        tile[r][tx] = W[(size_t)(k0 + r) * 512 + n0 + tx];
    __syncthreads();

    const float scale = (z == 0) ? 0.04419417382415922f : 1.0f;
    for (int r = ty; r < 32; r += 8) {
        int n = n0 + r;
        int k = k0 + tx;
        g_wf[((size_t)(z * 512 + n)) * 1024 + k] = __float2half_rn(tile[tx][r] * scale);
    }
}

// ---------------------------------------------------------------------------
// QKV GEMM via mma.sync fp16 (single precision), A-fragment pipelined.
// (unchanged from R13 — measured good)
// ---------------------------------------------------------------------------
#define GF_BUF 20480
#define GF_SMEM (2 * GF_BUF)

__device__ __forceinline__ void gemm_issue(unsigned sb, int buf, int m0, int nbase,
                                           int k0, int tid)
{
    unsigned base = sb + buf * GF_BUF;
#pragma unroll
    for (int i = 0; i < 4; i++) {
        int idx = tid + i * 256;          // 0..1023
        int which = idx >> 9;             // 0:A 1:B
        int u = idx & 511;
        int row = u >> 2;                 // 0..127
        int c = u & 3;                    // 16B unit within 32 k (64B)
        const __half* src = which
            ? (g_wf + (size_t)(nbase + row) * 1024 + k0 + c * 8)
            : (g_xf + (size_t)(m0 + row) * 1024 + k0 + c * 8);
        cpa16(base + which * 10240 + row * 80 + c * 16, src);
    }
    cp_commit();
}

__global__ __launch_bounds__(256, 2)
void qkv_hmma()
{
    extern __shared__ char smem[];
    unsigned sb = smem_u32(smem);
    const int tid  = threadIdx.x;
    const int lane = tid & 31;
    const int w    = tid >> 5;
    const int wm   = w >> 2;
    const int wn   = w & 3;
    const int nbase = blockIdx.x * 128;
    const int m0    = blockIdx.y * 128;

    float acc[4][4][4];
#pragma unroll
    for (int i = 0; i < 4; i++)
#pragma unroll
        for (int j = 0; j < 4; j++)
#pragma unroll
            for (int k = 0; k < 4; k++) acc[i][j][k] = 0.0f;

    const int mrowA = (lane & 7) + ((lane >> 3) & 1) * 8;
    const int kcA   = (lane >> 4) & 1;
    const int nrowB = (lane & 7) + ((lane >> 4) & 1) * 8;
    const int kcB   = (lane >> 3) & 1;
    const unsigned aoff = (wm * 64 + mrowA) * 80 + kcA * 16;
    const unsigned boff = 10240u + (wn * 32 + nrowB) * 80 + kcB * 16;

    gemm_issue(sb, 0, m0, nbase, 0, tid);

    for (int ch = 0; ch < 32; ++ch) {
        if (ch + 1 < 32) {
            gemm_issue(sb, (ch + 1) & 1, m0, nbase, (ch + 1) * 32, tid);
            cp_wait<1>();
        } else {
            cp_wait<0>();
        }
        __syncthreads();

        unsigned base = sb + (ch & 1) * GF_BUF;
#pragma unroll
        for (int ks = 0; ks < 2; ks++) {
            unsigned B8[8];
            ldsm4(&B8[0], base + boff + ks * 32);
            ldsm4(&B8[4], base + boff + 16 * 80 + ks * 32);
            unsigned Ab[2][4];
            ldsm4(Ab[0], base + aoff + ks * 32);
#pragma unroll
            for (int mt = 0; mt < 4; mt++) {
                int cur = mt & 1;
                if (mt < 3)
                    ldsm4(Ab[cur ^ 1], base + aoff + (mt + 1) * (16 * 80) + ks * 32);
#pragma unroll
                for (int nt = 0; nt < 4; nt++)
                    mma_f16(acc[mt][nt], Ab[cur], B8[nt * 2], B8[nt * 2 + 1]);
            }
        }
        __syncthreads();
    }

    // Epilogue: fp32 acc -> fp16 stores
    const int z = nbase >> 9;
    __half* Xf = (z == 0) ? g_qf : ((z == 1) ? g_kf : g_vf);
    const int colb = (nbase & 511) + wn * 32;
    const int gid = lane >> 2, tig = lane & 3;
#pragma unroll
    for (int mt = 0; mt < 4; mt++) {
#pragma unroll
        for (int nt = 0; nt < 4; nt++) {
            int row = m0 + wm * 64 + mt * 16 + gid;
            int col = colb + nt * 8 + tig * 2;
#pragma unroll
            for (int rr = 0; rr < 2; rr++) {
                size_t o = (size_t)(row + rr * 8) * 512 + col;
                *(__half2*)(Xf + o) =
                    __floats2half2_rn(acc[mt][nt][rr * 2 + 0], acc[mt][nt][rr * 2 + 1]);
            }
        }
    }
}

// ---------------------------------------------------------------------------
// fp16 flash attention + fused LayerNorm — 2 CTAs/SM, 4 RESIDENT KV chunks.
// All 4 x 128-d chunks of the 64-key tile live in smem at once:
//   S phase = 32 uninterrupted MMA steps; PV = 16 uninterrupted steps.
// V loads issued right after S reads K; overlap with softmax.
// Next-tile K loads issued after PV. ~6 barriers/tile (was 16).
// smem: Q 33280 | KV 4x17408 | S/P 8704 | stats -> 112896 B (2 CTAs/SM).
// ---------------------------------------------------------------------------
#define SD 68        // S pitch fp32
#define PP 72        // P pitch fp16 (144B, odd*16B)

#define OQ  0                    /* 32 x 1040B = 33280 */
#define OCB 33280                /* 4 bufs x 17408 -> 102912 */
#define OSP 102912               /* S 32x68 fp32 (8704), P overlays */
#define OPH 102912               /* fp16 32x72 = 4608 */
#define OAL 111616               /* fp32 32 */
#define OLL 111744               /* fp32 32 */
#define ORS 111872               /* fp32 32x4 */
#define ORQ 112384               /* fp32 32x4 */
#define ATTN_SMEM 112896

#define NEG_INF __int_as_float(0xff800000)

// Load one 64-key x 128-d fp16 chunk of K or V into buffer `buf` (0..3).
__device__ __forceinline__ void attn_load_chunk(unsigned sb, int buf,
                                                const __half* Xf,
                                                size_t srow0, int dc, int tid)
{
#pragma unroll
    for (int i = 0; i < 4; i++) {
        int idx = tid + i * 256;          // 0..1023
        int row = idx >> 4;               // 0..63 (key)
        int c = idx & 15;                 // 16B unit within 128 d (256B)
        const __half* src = Xf + (srow0 + row) * 512 + dc * 128 + c * 8;
        unsigned dst = sb + OCB + buf * 17408 + row * 272 + c * 16;
        cpa16(dst, src);
    }
    cp_commit();
}

__global__ __launch_bounds__(256, 2)
void attn_mma(const float* __restrict__ gamma, const float* __restrict__ beta,
              float* __restrict__ out)
{
    extern __shared__ char smc[];
    unsigned sb = smem_u32(smc);
    float* S    = (float*)(smc + OSP);
    float* AL   = (float*)(smc + OAL);
    float* LL   = (float*)(smc + OLL);
    float* RS   = (float*)(smc + ORS);
    float* RQ   = (float*)(smc + ORQ);
    __half* PH  = (__half*)(smc + OPH);

    const int b   = blockIdx.y;
    const int qb  = gridDim.x - 1 - blockIdx.x;     // heavy tiles first
    const int tid = threadIdx.x;
    const int lane = tid & 31;
    const int w    = tid >> 5;      // 0..7
    const int rh   = w >> 2;        // 0..1 (16-row group)
    const int cg   = w & 3;         // S col group (16 cols)
    const int vg   = w & 3;         // PV col group (32 d-cols per 128-d chunk)
    const int ti = tid >> 4;        // 0..15 -> rows 2ti, 2ti+1
    const int tj = tid & 15;        // cols 4tj..4tj+3

    const size_t qrow0 = (size_t)b * SEQ + (size_t)qb * 32;

    // --- load Q (32 x 512 fp16): 8 units per thread (1 commit group) ---
#pragma unroll
    for (int i = 0; i < 8; i++) {
        int idx = tid + i * 256;          // 0..2047
        int row = idx >> 6;               // 0..31
        int c = idx & 63;
        const __half* src = g_qf + (qrow0 + row) * 512 + c * 8;
        unsigned dst = sb + OQ + row * 1040 + c * 16;
        cpa16(dst, src);
    }
    cp_commit();

    float acc[4][4][4];
#pragma unroll
    for (int d = 0; d < 4; d++)
#pragma unroll
        for (int nt = 0; nt < 4; nt++)
#pragma unroll
            for (int k = 0; k < 4; k++) acc[d][nt][k] = 0.0f;

    float m0r = NEG_INF, m1r = NEG_INF;
    float l0r = 0.0f,    l1r = 0.0f;

    const unsigned qrow_a = rh * 16 + (lane & 7) + ((lane >> 3) & 1) * 8;
    const unsigned kca    = ((lane >> 4) & 1) * 8;
    const unsigned krow4  = cg * 16 + ((lane >> 4) & 1) * 8 + (lane & 7);
    const unsigned kc4    = ((lane >> 3) & 1) * 8;
    const unsigned prow_a = qrow_a;
    const unsigned psel   = ((lane >> 4) & 1) * 8;
    const unsigned vsrow  = ((lane >> 3) & 1) * 8 + (lane & 7);
    const unsigned vdoff  = ((lane >> 4) & 1) * 8;

    const int jbmax = qb >> 1;   // 64-key tiles; diagonal tile = jbmax

    // prologue: issue all 4 K chunks of jb=0
#pragma unroll
    for (int dc = 0; dc < 4; dc++)
        attn_load_chunk(sb, dc, g_kf, (size_t)b * SEQ, dc, tid);

    for (int jb = 0; jb <= jbmax; jb++) {
        const size_t srow0 = (size_t)b * SEQ + (size_t)jb * 64;
        const bool last = (jb == jbmax);

        // ---- wait for all K chunks (+Q on first iter), then one long S burst
        cp_wait<0>();
        __syncthreads();

        float s0[4] = {0, 0, 0, 0};
        float s1[4] = {0, 0, 0, 0};
#pragma unroll
        for (int dc = 0; dc < 4; dc++) {
            unsigned kb = sb + OCB + dc * 17408;
#pragma unroll
            for (int ks = 0; ks < 8; ks++) {
                unsigned qcol = (dc * 128 + ks * 16 + kca) * 2;
                unsigned Qf[4], Kf[4];
                ldsm4(Qf, sb + OQ + qrow_a * 1040 + qcol);
                unsigned kcol = (ks * 16 + kc4) * 2;
                ldsm4(Kf, kb + krow4 * 272 + kcol);
                mma_f16(s0, Qf, Kf[0], Kf[1]);
                mma_f16(s1, Qf, Kf[2], Kf[3]);
            }
        }
        // write S fragments
        {
            int r  = lane >> 2;
            int c2 = (lane & 3) * 2;
            int row0 = rh * 16 + r;
            int col0 = cg * 16 + c2;
            *(float2*)&S[row0 * SD + col0]           = make_float2(s0[0], s0[1]);
            *(float2*)&S[(row0 + 8) * SD + col0]     = make_float2(s0[2], s0[3]);
            *(float2*)&S[row0 * SD + col0 + 8]       = make_float2(s1[0], s1[1]);
            *(float2*)&S[(row0 + 8) * SD + col0 + 8] = make_float2(s1[2], s1[3]);
        }
        __syncthreads();   // S visible; all warps done reading K buffers

        // issue all 4 V chunks into the (now free) buffers — overlaps softmax
#pragma unroll
        for (int dc = 0; dc < 4; dc++)
            attn_load_chunk(sb, dc, g_vf, srow0, dc, tid);

        // ---- softmax ----
        {
            float4 v0 = *(float4*)&S[(2 * ti) * SD + 4 * tj];
            float4 v1 = *(float4*)&S[(2 * ti + 1) * SD + 4 * tj];
            float a0[4] = {v0.x, v0.y, v0.z, v0.w};
            float a1[4] = {v1.x, v1.y, v1.z, v1.w};

            if (jb == jbmax) {
                int qi0 = qb * 32 + 2 * ti;
                int kj  = jb * 64 + 4 * tj;
#pragma unroll
                for (int c = 0; c < 4; c++) {
                    if (kj + c > qi0)     a0[c] = NEG_INF;
                    if (kj + c > qi0 + 1) a1[c] = NEG_INF;
                }
            }

            float r0 = fmaxf(fmaxf(a0[0], a0[1]), fmaxf(a0[2], a0[3]));
            float r1 = fmaxf(fmaxf(a1[0], a1[1]), fmaxf(a1[2], a1[3]));
#pragma unroll
            for (int off = 1; off < 16; off <<= 1) {
                r0 = fmaxf(r0, __shfl_xor_sync(0xffffffffu, r0, off));
                r1 = fmaxf(r1, __shfl_xor_sync(0xffffffffu, r1, off));
            }
            float mn0 = fmaxf(m0r, r0);
            float mn1 = fmaxf(m1r, r1);
            float al0 = __expf(m0r - mn0);
            float al1 = __expf(m1r - mn1);

            float p0[4], p1[4];
#pragma unroll
            for (int c = 0; c < 4; c++) {
                p0[c] = __expf(a0[c] - mn0);
                p1[c] = __expf(a1[c] - mn1);
            }
            float rs0 = (p0[0] + p0[1]) + (p0[2] + p0[3]);
            float rs1 = (p1[0] + p1[1]) + (p1[2] + p1[3]);
#pragma unroll
            for (int off = 1; off < 16; off <<= 1) {
                rs0 += __shfl_xor_sync(0xffffffffu, rs0, off);
                rs1 += __shfl_xor_sync(0xffffffffu, rs1, off);
            }
            l0r = al0 * l0r + rs0;  m0r = mn0;
            l1r = al1 * l1r + rs1;  m1r = mn1;

            if (tj == 0) {
                AL[2 * ti]     = al0;
                AL[2 * ti + 1] = al1;
                LL[2 * ti]     = l0r;
                LL[2 * ti + 1] = l1r;
            }
            __syncthreads();   // all S reads done before P overlays S

            *(__half2*)&PH[(2 * ti) * PP + 4 * tj]         = __floats2half2_rn(p0[0], p0[1]);
            *(__half2*)&PH[(2 * ti) * PP + 4 * tj + 2]     = __floats2half2_rn(p0[2], p0[3]);
            *(__half2*)&PH[(2 * ti + 1) * PP + 4 * tj]     = __floats2half2_rn(p1[0], p1[1]);
            *(__half2*)&PH[(2 * ti + 1) * PP + 4 * tj + 2] = __floats2half2_rn(p1[2], p1[3]);
        }
        __syncthreads();   // P + AL visible

        // hoist P fragments into registers
        unsigned Pf[4][4];
#pragma unroll
        for (int ks2 = 0; ks2 < 4; ks2++) {
            unsigned pcol = (ks2 * 16 + psel) * 2;
            ldsm4(Pf[ks2], sb + OPH + prow_a * 144 + pcol);
        }

        // scale accumulators by alpha
        {
            float a0 = AL[rh * 16 + (lane >> 2)];
            float a1 = AL[rh * 16 + (lane >> 2) + 8];
#pragma unroll
            for (int d = 0; d < 4; d++)
#pragma unroll
                for (int nt = 0; nt < 4; nt++) {
                    acc[d][nt][0] *= a0; acc[d][nt][1] *= a0;
                    acc[d][nt][2] *= a1; acc[d][nt][3] *= a1;
                }
        }

        // ---- wait for all V chunks, then one long PV burst ----
        cp_wait<0>();
        __syncthreads();
#pragma unroll
        for (int dc = 0; dc < 4; dc++) {
            unsigned vb = sb + OCB + dc * 17408;
#pragma unroll
            for (int ks2 = 0; ks2 < 4; ks2++) {
                unsigned vrow = (ks2 * 16 + vsrow) * 272;
#pragma unroll
                for (int ng2 = 0; ng2 < 2; ng2++) {
                    unsigned vcol = (vg * 32 + ng2 * 16 + vdoff) * 2;
                    unsigned Vf[4];
                    ldsm4t(Vf, vb + vrow + vcol);
                    mma_f16(acc[dc][ng2 * 2],     Pf[ks2], Vf[0], Vf[1]);
                    mma_f16(acc[dc][ng2 * 2 + 1], Pf[ks2], Vf[2], Vf[3]);
                }
            }
        }
        __syncthreads();   // all warps done reading V buffers

        // issue next tile's K chunks
        if (!last) {
#pragma unroll
            for (int dc = 0; dc < 4; dc++)
                attn_load_chunk(sb, dc, g_kf, srow0 + 64, dc, tid);
        }
    }

    // ---- epilogue: 1/l, LayerNorm, store ----
    {
        int r  = lane >> 2;
        int c2 = (lane & 3) * 2;
        int row0 = rh * 16 + r;
        int row1 = row0 + 8;
        float linv0 = 1.0f / LL[row0];
        float linv1 = 1.0f / LL[row1];
        float s0 = 0.f, q0 = 0.f, s1 = 0.f, q1 = 0.f;
#pragma unroll
        for (int d = 0; d < 4; d++)
#pragma unroll
            for (int nt = 0; nt < 4; nt++) {
                acc[d][nt][0] *= linv0; acc[d][nt][1] *= linv0;
                acc[d][nt][2] *= linv1; acc[d][nt][3] *= linv1;
                s0 += acc[d][nt][0] + acc[d][nt][1];
                q0 += acc[d][nt][0] * acc[d][nt][0] + acc[d][nt][1] * acc[d][nt][1];
                s1 += acc[d][nt][2] + acc[d][nt][3];
                q1 += acc[d][nt][2] * acc[d][nt][2] + acc[d][nt][3] * acc[d][nt][3];
            }
#pragma unroll
        for (int off = 1; off < 4; off <<= 1) {
            s0 += __shfl_xor_sync(0xffffffffu, s0, off);
            q0 += __shfl_xor_sync(0xffffffffu, q0, off);
            s1 += __shfl_xor_sync(0xffffffffu, s1, off);
            q1 += __shfl_xor_sync(0xffffffffu, q1, off);
        }
        if ((lane & 3) == 0) {
            RS[row0 * 4 + vg] = s0;  RQ[row0 * 4 + vg] = q0;
            RS[row1 * 4 + vg] = s1;  RQ[row1 * 4 + vg] = q1;
        }
        __syncthreads();
        float ts0 = RS[row0 * 4] + RS[row0 * 4 + 1] + RS[row0 * 4 + 2] + RS[row0 * 4 + 3];
        float tq0 = RQ[row0 * 4] + RQ[row0 * 4 + 1] + RQ[row0 * 4 + 2] + RQ[row0 * 4 + 3];
        float ts1 = RS[row1 * 4] + RS[row1 * 4 + 1] + RS[row1 * 4 + 2] + RS[row1 * 4 + 3];
        float tq1 = RQ[row1 * 4] + RQ[row1 * 4 + 1] + RQ[row1 * 4 + 2] + RQ[row1 * 4 + 3];
        const float invD = 1.0f / (float)DIM;
        float mu0 = ts0 * invD, var0 = tq0 * invD - mu0 * mu0;
        float mu1 = ts1 * invD, var1 = tq1 * invD - mu1 * mu1;
        float rstd0 = rsqrtf(var0 + 1e-5f);
        float rstd1 = rsqrtf(var1 + 1e-5f);

        size_t ob0 = (qrow0 + row0) * 512;
        size_t ob1 = (qrow0 + row1) * 512;
#pragma unroll
        for (int d = 0; d < 4; d++)
#pragma unroll
            for (int nt = 0; nt < 4; nt++) {
                int col = d * 128 + vg * 32 + nt * 8 + c2;
                float g0 = gamma[col], g1 = gamma[col + 1];
                float be0 = beta[col], be1 = beta[col + 1];
                float2 o0 = make_float2((acc[d][nt][0] - mu0) * rstd0 * g0 + be0,
                                        (acc[d][nt][1] - mu0) * rstd0 * g1 + be1);
                float2 o1 = make_float2((acc[d][nt][2] - mu1) * rstd1 * g0 + be0,
                                        (acc[d][nt][3] - mu1) * rstd1 * g1 + be1);
                *(float2*)(out + ob0 + col) = o0;
                *(float2*)(out + ob1 + col) = o1;
            }
    }
}

// ---------------------------------------------------------------------------
// Launch
// ---------------------------------------------------------------------------
extern "C" void kernel_launch(void* const* d_in, const int* in_sizes, int n_in,
                              void* d_out, int out_size)
{
    const float* x0    = (const float*)d_in[0];
    const float* x1    = (const float*)d_in[1];
    const float* Wq    = (const float*)d_in[2];
    const float* Wk    = (const float*)d_in[3];
    const float* Wv    = (const float*)d_in[4];
    const float* gamma = (const float*)d_in[5];
    const float* beta  = (const float*)d_in[6];
    float* out = (float*)d_out;

    cudaFuncSetAttribute(qkv_hmma, cudaFuncAttributeMaxDynamicSharedMemorySize, GF_SMEM);
    cudaFuncSetAttribute(attn_mma, cudaFuncAttributeMaxDynamicSharedMemorySize, ATTN_SMEM);

    conv_x<<<MTOT, 256>>>(x0, x1);
    conv_w<<<dim3(16, 32, 3), dim3(32, 8)>>>(Wq, Wk, Wv);
    qkv_hmma<<<dim3(12, 128), 256, GF_SMEM>>>();
    attn_mma<<<dim3(SEQ / 32, BATCH), 256, ATTN_SMEM>>>(gamma, beta, out);
}

// round 15
// speedup vs baseline: 2.3133x; 1.0123x over previous
#include <cuda_runtime.h>
#include <cuda_bf16.h>
#include <cuda_fp16.h>
#include <math.h>

// Problem constants
#define BATCH 8
#define SEQ   2048
#define DIM   512
#define KDIM  1024
#define MTOT  (BATCH*SEQ)   // 16384

// Scratch (no cudaMalloc allowed)
__device__ __half g_xf[(size_t)MTOT * KDIM];
__device__ __half g_wf[(size_t)3 * DIM * KDIM];
__device__ __half g_qf[(size_t)MTOT * DIM];
__device__ __half g_kf[(size_t)MTOT * DIM];
__device__ __half g_vf[(size_t)MTOT * DIM];

// ---------------------------------------------------------------------------
// helpers
// ---------------------------------------------------------------------------
__device__ __forceinline__ unsigned smem_u32(const void* p) {
    unsigned a;
    asm("{ .reg .u64 t; cvta.to.shared.u64 t, %1; cvt.u32.u64 %0, t; }" : "=r"(a) : "l"(p));
    return a;
}
__device__ __forceinline__ void cpa16(unsigned dst, const void* src) {
    asm volatile("cp.async.cg.shared.global [%0], [%1], 16;"
                 :: "r"(dst), "l"(__cvta_generic_to_global(src)) : "memory");
}
__device__ __forceinline__ void cp_commit() {
    asm volatile("cp.async.commit_group;" ::: "memory");
}
template <int N>
__device__ __forceinline__ void cp_wait() {
    asm volatile("cp.async.wait_group %0;" :: "n"(N) : "memory");
}
__device__ __forceinline__ void ldsm4(unsigned* r, unsigned addr) {
    asm volatile("ldmatrix.sync.aligned.m8n8.x4.shared.b16 {%0,%1,%2,%3}, [%4];"
                 : "=r"(r[0]), "=r"(r[1]), "=r"(r[2]), "=r"(r[3]) : "r"(addr));
}
__device__ __forceinline__ void ldsm4t(unsigned* r, unsigned addr) {
    asm volatile("ldmatrix.sync.aligned.m8n8.x4.trans.shared.b16 {%0,%1,%2,%3}, [%4];"
                 : "=r"(r[0]), "=r"(r[1]), "=r"(r[2]), "=r"(r[3]) : "r"(addr));
}
__device__ __forceinline__ void mma_f16(float* c, const unsigned* a,
                                        unsigned b0, unsigned b1) {
    asm volatile(
        "mma.sync.aligned.m16n8k16.row.col.f32.f16.f16.f32 "
        "{%0,%1,%2,%3}, {%4,%5,%6,%7}, {%8,%9}, {%0,%1,%2,%3};"
        : "+f"(c[0]), "+f"(c[1]), "+f"(c[2]), "+f"(c[3])
        : "r"(a[0]), "r"(a[1]), "r"(a[2]), "r"(a[3]), "r"(b0), "r"(b1));
}

// ---------------------------------------------------------------------------
// Conversion: x0|x1 -> fp16, row-major [MTOT][1024]
// ---------------------------------------------------------------------------
__global__ __launch_bounds__(256)
void conv_x(const float* __restrict__ x0, const float* __restrict__ x1)
{
    unsigned t = blockIdx.x * 256u + threadIdx.x;
    unsigned m  = t >> 8;
    unsigned k4 = (t & 255u) * 4u;
    float4 v = (k4 < 512u)
        ? *(const float4*)(x0 + (size_t)m * 512 + k4)
        : *(const float4*)(x1 + (size_t)m * 512 + (k4 - 512u));
    __half2* d = (__half2*)(g_xf + (size_t)m * 1024 + k4);
    d[0] = __floats2half2_rn(v.x, v.y);
    d[1] = __floats2half2_rn(v.z, v.w);
}

// ---------------------------------------------------------------------------
// W[k][n] -> W^T fp16, n-major rows (q scaled by 1/sqrt(D))
// ---------------------------------------------------------------------------
__global__ __launch_bounds__(256)
void conv_w(const float* __restrict__ Wq, const float* __restrict__ Wk,
            const float* __restrict__ Wv)
{
    __shared__ float tile[32][33];
    const int z  = blockIdx.z;
    const float* __restrict__ W = (z == 0) ? Wq : ((z == 1) ? Wk : Wv);
    const int n0 = blockIdx.x * 32;
    const int k0 = blockIdx.y * 32;
    const int tx = threadIdx.x;
    const int ty = threadIdx.y;

    for (int r = ty; r < 32; r += 8)
        tile[r][tx] = W[(size_t)(k0 + r) * 512 + n0 + tx];
    __syncthreads();

    const float scale = (z == 0) ? 0.04419417382415922f : 1.0f;
    for (int r = ty; r < 32; r += 8) {
        int n = n0 + r;
        int k = k0 + tx;
        g_wf[((size_t)(z * 512 + n)) * 1024 + k] = __float2half_rn(tile[tx][r] * scale);
    }
}

// ---------------------------------------------------------------------------
// QKV GEMM via mma.sync fp16, A-fragment pipelined. (unchanged — measured good)
// ---------------------------------------------------------------------------
#define GF_BUF 20480
#define GF_SMEM (2 * GF_BUF)

__device__ __forceinline__ void gemm_issue(unsigned sb, int buf, int m0, int nbase,
                                           int k0, int tid)
{
    unsigned base = sb + buf * GF_BUF;
#pragma unroll
    for (int i = 0; i < 4; i++) {
        int idx = tid + i * 256;
        int which = idx >> 9;
        int u = idx & 511;
        int row = u >> 2;
        int c = u & 3;
        const __half* src = which
            ? (g_wf + (size_t)(nbase + row) * 1024 + k0 + c * 8)
            : (g_xf + (size_t)(m0 + row) * 1024 + k0 + c * 8);
        cpa16(base + which * 10240 + row * 80 + c * 16, src);
    }
    cp_commit();
}

__global__ __launch_bounds__(256, 2)
void qkv_hmma()
{
    extern __shared__ char smem[];
    unsigned sb = smem_u32(smem);
    const int tid  = threadIdx.x;
    const int lane = tid & 31;
    const int w    = tid >> 5;
    const int wm   = w >> 2;
    const int wn   = w & 3;
    const int nbase = blockIdx.x * 128;
    const int m0    = blockIdx.y * 128;

    float acc[4][4][4];
#pragma unroll
    for (int i = 0; i < 4; i++)
#pragma unroll
        for (int j = 0; j < 4; j++)
#pragma unroll
            for (int k = 0; k < 4; k++) acc[i][j][k] = 0.0f;

    const int mrowA = (lane & 7) + ((lane >> 3) & 1) * 8;
    const int kcA   = (lane >> 4) & 1;
    const int nrowB = (lane & 7) + ((lane >> 4) & 1) * 8;
    const int kcB   = (lane >> 3) & 1;
    const unsigned aoff = (wm * 64 + mrowA) * 80 + kcA * 16;
    const unsigned boff = 10240u + (wn * 32 + nrowB) * 80 + kcB * 16;

    gemm_issue(sb, 0, m0, nbase, 0, tid);

    for (int ch = 0; ch < 32; ++ch) {
        if (ch + 1 < 32) {
            gemm_issue(sb, (ch + 1) & 1, m0, nbase, (ch + 1) * 32, tid);
            cp_wait<1>();
        } else {
            cp_wait<0>();
        }
        __syncthreads();

        unsigned base = sb + (ch & 1) * GF_BUF;
#pragma unroll
        for (int ks = 0; ks < 2; ks++) {
            unsigned B8[8];
            ldsm4(&B8[0], base + boff + ks * 32);
            ldsm4(&B8[4], base + boff + 16 * 80 + ks * 32);
            unsigned Ab[2][4];
            ldsm4(Ab[0], base + aoff + ks * 32);
#pragma unroll
            for (int mt = 0; mt < 4; mt++) {
                int cur = mt & 1;
                if (mt < 3)
                    ldsm4(Ab[cur ^ 1], base + aoff + (mt + 1) * (16 * 80) + ks * 32);
#pragma unroll
                for (int nt = 0; nt < 4; nt++)
                    mma_f16(acc[mt][nt], Ab[cur], B8[nt * 2], B8[nt * 2 + 1]);
            }
        }
        __syncthreads();
    }

    const int z = nbase >> 9;
    __half* Xf = (z == 0) ? g_qf : ((z == 1) ? g_kf : g_vf);
    const int colb = (nbase & 511) + wn * 32;
    const int gid = lane >> 2, tig = lane & 3;
#pragma unroll
    for (int mt = 0; mt < 4; mt++) {
#pragma unroll
        for (int nt = 0; nt < 4; nt++) {
            int row = m0 + wm * 64 + mt * 16 + gid;
            int col = colb + nt * 8 + tig * 2;
#pragma unroll
            for (int rr = 0; rr < 2; rr++) {
                size_t o = (size_t)(row + rr * 8) * 512 + col;
                *(__half2*)(Xf + o) =
                    __floats2half2_rn(acc[mt][nt][rr * 2 + 0], acc[mt][nt][rr * 2 + 1]);
            }
        }
    }
}

// ---------------------------------------------------------------------------
// fp16 flash attention + fused LayerNorm — 2 CTAs/SM, 4 resident KV chunks,
// WIDE warp tiles to cut ldsm/mma:
//   S phase : warp = 32 rows x 16 cols x half-K (kh=w>>2, cg=w&3);
//             per step 2 Q-ldsm + 1 K-ldsm -> 4 MMAs. K-halves combined by
//             smem read-modify-write (kh0 stores, sync, kh1 adds).
//   PV phase: warp = 32 rows x 64 d-cols (wv=w); per k-step 2 P-ldsm +
//             4 V-ldsm -> 16 MMAs.
// ---------------------------------------------------------------------------
#define SD 68        // S pitch fp32
#define PP 72        // P pitch fp16

#define OQ  0                    /* 32 x 1040B = 33280 */
#define OCB 33280                /* 4 bufs x 17408 -> 102912 */
#define OSP 102912               /* S 32x68 fp32 (8704), P overlays */
#define OPH 102912               /* fp16 32x72 = 4608 */
#define OAL 111616               /* fp32 32 */
#define OLL 111744               /* fp32 32 */
#define ORS 111872               /* fp32 32x8 = 1024 */
#define ORQ 112896               /* fp32 32x8 = 1024 */
#define ATTN_SMEM 113920

#define NEG_INF __int_as_float(0xff800000)

__device__ __forceinline__ void attn_load_chunk(unsigned sb, int buf,
                                                const __half* Xf,
                                                size_t srow0, int dc, int tid)
{
#pragma unroll
    for (int i = 0; i < 4; i++) {
        int idx = tid + i * 256;
        int row = idx >> 4;
        int c = idx & 15;
        const __half* src = Xf + (srow0 + row) * 512 + dc * 128 + c * 8;
        unsigned dst = sb + OCB + buf * 17408 + row * 272 + c * 16;
        cpa16(dst, src);
    }
    cp_commit();
}

__global__ __launch_bounds__(256, 2)
void attn_mma(const float* __restrict__ gamma, const float* __restrict__ beta,
              float* __restrict__ out)
{
    extern __shared__ char smc[];
    unsigned sb = smem_u32(smc);
    float* S    = (float*)(smc + OSP);
    float* AL   = (float*)(smc + OAL);
    float* LL   = (float*)(smc + OLL);
    float* RS   = (float*)(smc + ORS);
    float* RQ   = (float*)(smc + ORQ);
    __half* PH  = (__half*)(smc + OPH);

    const int b   = blockIdx.y;
    const int qb  = gridDim.x - 1 - blockIdx.x;
    const int tid = threadIdx.x;
    const int lane = tid & 31;
    const int w    = tid >> 5;      // 0..7
    const int kh   = w >> 2;        // S: half-K selector
    const int cg   = w & 3;         // S: col group (16 cols)
    const int ti = tid >> 4;        // softmax rows 2ti, 2ti+1
    const int tj = tid & 15;        // softmax cols 4tj..4tj+3

    const size_t qrow0 = (size_t)b * SEQ + (size_t)qb * 32;

    // --- load Q (32 x 512 fp16) ---
#pragma unroll
    for (int i = 0; i < 8; i++) {
        int idx = tid + i * 256;
        int row = idx >> 6;
        int c = idx & 63;
        const __half* src = g_qf + (qrow0 + row) * 512 + c * 8;
        unsigned dst = sb + OQ + row * 1040 + c * 16;
        cpa16(dst, src);
    }
    cp_commit();

    // PV accumulator: acc[mh][oct][4] — rows mh*16 + {r, r+8}, cols w*64+oct*8
    float acc[2][8][4];
#pragma unroll
    for (int mh = 0; mh < 2; mh++)
#pragma unroll
        for (int o = 0; o < 8; o++)
#pragma unroll
            for (int k = 0; k < 4; k++) acc[mh][o][k] = 0.0f;

    float m0r = NEG_INF, m1r = NEG_INF;
    float l0r = 0.0f,    l1r = 0.0f;

    // lane address components
    const unsigned frow  = (lane & 7) + ((lane >> 3) & 1) * 8;   // A-frag row 0..15
    const unsigned kca   = ((lane >> 4) & 1) * 8;
    const unsigned krow  = cg * 16 + ((lane >> 4) & 1) * 8 + (lane & 7);
    const unsigned kc4   = ((lane >> 3) & 1) * 8;
    const unsigned psel  = ((lane >> 4) & 1) * 8;
    const unsigned vsrow = ((lane >> 3) & 1) * 8 + (lane & 7);
    const unsigned vdoff = ((lane >> 4) & 1) * 8;

    const int jbmax = qb >> 1;

    // prologue: issue all 4 K chunks of jb=0
#pragma unroll
    for (int dc = 0; dc < 4; dc++)
        attn_load_chunk(sb, dc, g_kf, (size_t)b * SEQ, dc, tid);

    for (int jb = 0; jb <= jbmax; jb++) {
        const size_t srow0 = (size_t)b * SEQ + (size_t)jb * 64;
        const bool last = (jb == jbmax);

        cp_wait<0>();
        __syncthreads();

        // ---- S phase: warp covers 32 rows x 16 cols over its half of K ----
        float s[2][2][4];
#pragma unroll
        for (int mh = 0; mh < 2; mh++)
#pragma unroll
            for (int o = 0; o < 2; o++)
#pragma unroll
                for (int k = 0; k < 4; k++) s[mh][o][k] = 0.0f;

#pragma unroll
        for (int dc2 = 0; dc2 < 2; dc2++) {
            int dc = kh * 2 + dc2;
            unsigned kb = sb + OCB + dc * 17408;
#pragma unroll
            for (int ks = 0; ks < 8; ks++) {
                unsigned qcol = (dc * 128 + ks * 16 + kca) * 2;
                unsigned Q0[4], Q1[4], Kf[4];
                ldsm4(Q0, sb + OQ + frow * 1040 + qcol);
                ldsm4(Q1, sb + OQ + (frow + 16) * 1040 + qcol);
                unsigned kcol = (ks * 16 + kc4) * 2;
                ldsm4(Kf, kb + krow * 272 + kcol);
                mma_f16(s[0][0], Q0, Kf[0], Kf[1]);
                mma_f16(s[0][1], Q0, Kf[2], Kf[3]);
                mma_f16(s[1][0], Q1, Kf[0], Kf[1]);
                mma_f16(s[1][1], Q1, Kf[2], Kf[3]);
            }
        }

        // combine k-halves: kh0 stores, sync, kh1 adds
        {
            int r  = lane >> 2;
            int c2 = (lane & 3) * 2;
            if (kh == 0) {
#pragma unroll
                for (int mh = 0; mh < 2; mh++)
#pragma unroll
                    for (int o = 0; o < 2; o++) {
                        int row = mh * 16 + r;
                        int col = cg * 16 + o * 8 + c2;
                        *(float2*)&S[row * SD + col]       = make_float2(s[mh][o][0], s[mh][o][1]);
                        *(float2*)&S[(row + 8) * SD + col] = make_float2(s[mh][o][2], s[mh][o][3]);
                    }
            }
            __syncthreads();
            // issue V chunks (K buffers now free for all warps)
#pragma unroll
            for (int dc = 0; dc < 4; dc++)
                attn_load_chunk(sb, dc, g_vf, srow0, dc, tid);

            if (kh == 1) {
#pragma unroll
                for (int mh = 0; mh < 2; mh++)
#pragma unroll
                    for (int o = 0; o < 2; o++) {
                        int row = mh * 16 + r;
                        int col = cg * 16 + o * 8 + c2;
                        float2 a = *(float2*)&S[row * SD + col];
                        float2 bq = *(float2*)&S[(row + 8) * SD + col];
                        a.x += s[mh][o][0];  a.y += s[mh][o][1];
                        bq.x += s[mh][o][2]; bq.y += s[mh][o][3];
                        *(float2*)&S[row * SD + col]       = a;
                        *(float2*)&S[(row + 8) * SD + col] = bq;
                    }
            }
        }
        __syncthreads();

        // ---- softmax ----
        {
            float4 v0 = *(float4*)&S[(2 * ti) * SD + 4 * tj];
            float4 v1 = *(float4*)&S[(2 * ti + 1) * SD + 4 * tj];
            float a0[4] = {v0.x, v0.y, v0.z, v0.w};
            float a1[4] = {v1.x, v1.y, v1.z, v1.w};

            if (jb == jbmax) {
                int qi0 = qb * 32 + 2 * ti;
                int kj  = jb * 64 + 4 * tj;
#pragma unroll
                for (int c = 0; c < 4; c++) {
                    if (kj + c > qi0)     a0[c] = NEG_INF;
                    if (kj + c > qi0 + 1) a1[c] = NEG_INF;
                }
            }

            float r0 = fmaxf(fmaxf(a0[0], a0[1]), fmaxf(a0[2], a0[3]));
            float r1 = fmaxf(fmaxf(a1[0], a1[1]), fmaxf(a1[2], a1[3]));
#pragma unroll
            for (int off = 1; off < 16; off <<= 1) {
                r0 = fmaxf(r0, __shfl_xor_sync(0xffffffffu, r0, off));
                r1 = fmaxf(r1, __shfl_xor_sync(0xffffffffu, r1, off));
            }
            float mn0 = fmaxf(m0r, r0);
            float mn1 = fmaxf(m1r, r1);
            float al0 = __expf(m0r - mn0);
            float al1 = __expf(m1r - mn1);

            float p0[4], p1[4];
#pragma unroll
            for (int c = 0; c < 4; c++) {
                p0[c] = __expf(a0[c] - mn0);
                p1[c] = __expf(a1[c] - mn1);
            }
            float rs0 = (p0[0] + p0[1]) + (p0[2] + p0[3]);
            float rs1 = (p1[0] + p1[1]) + (p1[2] + p1[3]);
#pragma unroll
            for (int off = 1; off < 16; off <<= 1) {
                rs0 += __shfl_xor_sync(0xffffffffu, rs0, off);
                rs1 += __shfl_xor_sync(0xffffffffu, rs1, off);
            }
            l0r = al0 * l0r + rs0;  m0r = mn0;
            l1r = al1 * l1r + rs1;  m1r = mn1;

            if (tj == 0) {
                AL[2 * ti]     = al0;
                AL[2 * ti + 1] = al1;
                LL[2 * ti]     = l0r;
                LL[2 * ti + 1] = l1r;
            }
            __syncthreads();   // all S reads done before P overlays S

            *(__half2*)&PH[(2 * ti) * PP + 4 * tj]         = __floats2half2_rn(p0[0], p0[1]);
            *(__half2*)&PH[(2 * ti) * PP + 4 * tj + 2]     = __floats2half2_rn(p0[2], p0[3]);
            *(__half2*)&PH[(2 * ti + 1) * PP + 4 * tj]     = __floats2half2_rn(p1[0], p1[1]);
            *(__half2*)&PH[(2 * ti + 1) * PP + 4 * tj + 2] = __floats2half2_rn(p1[2], p1[3]);
        }
        __syncthreads();   // P + AL visible

        // scale accumulators by alpha (4 rows per thread)
        {
            int r = lane >> 2;
            float a0 = AL[r];
            float a1 = AL[r + 8];
            float a2 = AL[r + 16];
            float a3 = AL[r + 24];
#pragma unroll
            for (int o = 0; o < 8; o++) {
                acc[0][o][0] *= a0; acc[0][o][1] *= a0;
                acc[0][o][2] *= a1; acc[0][o][3] *= a1;
                acc[1][o][0] *= a2; acc[1][o][1] *= a2;
                acc[1][o][2] *= a3; acc[1][o][3] *= a3;
            }
        }

        // ---- PV: warp = 32 rows x 64 d-cols (wv = w) ----
        cp_wait<0>();
        __syncthreads();
        {
            unsigned vb = sb + OCB + (w >> 1) * 17408;
            unsigned vcb = (unsigned)((w & 1) * 64);
#pragma unroll
            for (int ks2 = 0; ks2 < 4; ks2++) {
                unsigned pcol = (ks2 * 16 + psel) * 2;
                unsigned Pf0[4], Pf1[4];
                ldsm4(Pf0, sb + OPH + frow * 144 + pcol);
                ldsm4(Pf1, sb + OPH + (frow + 16) * 144 + pcol);
                unsigned vrow = (ks2 * 16 + vsrow) * 272;
#pragma unroll
                for (int cq = 0; cq < 4; cq++) {
                    unsigned vcol = (vcb + cq * 16 + vdoff) * 2;
                    unsigned Vf[4];
                    ldsm4t(Vf, vb + vrow + vcol);
                    mma_f16(acc[0][cq * 2],     Pf0, Vf[0], Vf[1]);
                    mma_f16(acc[0][cq * 2 + 1], Pf0, Vf[2], Vf[3]);
                    mma_f16(acc[1][cq * 2],     Pf1, Vf[0], Vf[1]);
                    mma_f16(acc[1][cq * 2 + 1], Pf1, Vf[2], Vf[3]);
                }
            }
        }
        __syncthreads();

        if (!last) {
#pragma unroll
            for (int dc = 0; dc < 4; dc++)
                attn_load_chunk(sb, dc, g_kf, srow0 + 64, dc, tid);
        }
    }

    // ---- epilogue: 1/l, LayerNorm (8-warp reduction), store ----
    {
        int r  = lane >> 2;
        int c2 = (lane & 3) * 2;
        float linv[4] = {1.0f / LL[r], 1.0f / LL[r + 8],
                         1.0f / LL[r + 16], 1.0f / LL[r + 24]};
        float sm[4] = {0, 0, 0, 0}, sq[4] = {0, 0, 0, 0};
#pragma unroll
        for (int mh = 0; mh < 2; mh++)
#pragma unroll
            for (int o = 0; o < 8; o++) {
                acc[mh][o][0] *= linv[mh * 2];     acc[mh][o][1] *= linv[mh * 2];
                acc[mh][o][2] *= linv[mh * 2 + 1]; acc[mh][o][3] *= linv[mh * 2 + 1];
                sm[mh * 2]     += acc[mh][o][0] + acc[mh][o][1];
                sq[mh * 2]     += acc[mh][o][0] * acc[mh][o][0] + acc[mh][o][1] * acc[mh][o][1];
                sm[mh * 2 + 1] += acc[mh][o][2] + acc[mh][o][3];
                sq[mh * 2 + 1] += acc[mh][o][2] * acc[mh][o][2] + acc[mh][o][3] * acc[mh][o][3];
            }
#pragma unroll
        for (int off = 1; off < 4; off <<= 1) {
#pragma unroll
            for (int i = 0; i < 4; i++) {
                sm[i] += __shfl_xor_sync(0xffffffffu, sm[i], off);
                sq[i] += __shfl_xor_sync(0xffffffffu, sq[i], off);
            }
        }
        if ((lane & 3) == 0) {
#pragma unroll
            for (int i = 0; i < 4; i++) {
                int row = (i >> 1) * 16 + (i & 1) * 8 + r;
                RS[row * 8 + w] = sm[i];
                RQ[row * 8 + w] = sq[i];
            }
        }
        __syncthreads();

        const float invD = 1.0f / (float)DIM;
        float mu[4], rstd[4];
#pragma unroll
        for (int i = 0; i < 4; i++) {
            int row = (i >> 1) * 16 + (i & 1) * 8 + r;
            float ts = 0.f, tq = 0.f;
#pragma unroll
            for (int j = 0; j < 8; j++) { ts += RS[row * 8 + j]; tq += RQ[row * 8 + j]; }
            mu[i] = ts * invD;
            rstd[i] = rsqrtf(tq * invD - mu[i] * mu[i] + 1e-5f);
        }

#pragma unroll
        for (int mh = 0; mh < 2; mh++)
#pragma unroll
            for (int o = 0; o < 8; o++) {
                int col = w * 64 + o * 8 + c2;
                float g0 = gamma[col], g1 = gamma[col + 1];
                float be0 = beta[col], be1 = beta[col + 1];
                int i0 = mh * 2, i1 = mh * 2 + 1;
                size_t ob0 = (qrow0 + mh * 16 + r) * 512;
                size_t ob1 = (qrow0 + mh * 16 + r + 8) * 512;
                float2 o0 = make_float2((acc[mh][o][0] - mu[i0]) * rstd[i0] * g0 + be0,
                                        (acc[mh][o][1] - mu[i0]) * rstd[i0] * g1 + be1);
                float2 o1 = make_float2((acc[mh][o][2] - mu[i1]) * rstd[i1] * g0 + be0,
                                        (acc[mh][o][3] - mu[i1]) * rstd[i1] * g1 + be1);
                *(float2*)(out + ob0 + col) = o0;
                *(float2*)(out + ob1 + col) = o1;
            }
    }
}

// ---------------------------------------------------------------------------
// Launch
// ---------------------------------------------------------------------------
extern "C" void kernel_launch(void* const* d_in, const int* in_sizes, int n_in,
                              void* d_out, int out_size)
{
    const float* x0    = (const float*)d_in[0];
    const float* x1    = (const float*)d_in[1];
    const float* Wq    = (const float*)d_in[2];
    const float* Wk    = (const float*)d_in[3];
    const float* Wv    = (const float*)d_in[4];
    const float* gamma = (const float*)d_in[5];
    const float* beta  = (const float*)d_in[6];
    float* out = (float*)d_out;

    cudaFuncSetAttribute(qkv_hmma, cudaFuncAttributeMaxDynamicSharedMemorySize, GF_SMEM);
    cudaFuncSetAttribute(attn_mma, cudaFuncAttributeMaxDynamicSharedMemorySize, ATTN_SMEM);

    conv_x<<<MTOT, 256>>>(x0, x1);
    conv_w<<<dim3(16, 32, 3), dim3(32, 8)>>>(Wq, Wk, Wv);
    qkv_hmma<<<dim3(12, 128), 256, GF_SMEM>>>();
    attn_mma<<<dim3(SEQ / 32, BATCH), 256, ATTN_SMEM>>>(gamma, beta, out);
}